// round 8
// baseline (speedup 1.0000x reference)
#include <cuda_runtime.h>
#include <math.h>
#include <stdint.h>

// ---------------- problem constants ----------------
#define H_IN 2048
#define W_IN 2048
#define P1   1023            // after conv1(2046) + maxpool2
#define C2   1021            // after conv2
#define H2S  1024            // padded row stride for h2
#define C3   1019            // after conv3
#define NPIX (C3*C3)         // 1038361
#define PLANE (C3 * 1024)    // padded plane for h3
#define NBINS 8192
#define CANDMAX 4096
#define KTOP 512

typedef unsigned long long ull;

// ---------------- scratch (device globals) ----------
__device__ float g_pool1[10 * P1 * P1];
__device__ float g_h2p[16 * C2 * H2S];      // padded stride 1024
__device__ float g_h3[32 * PLANE];          // conv3 output, 32 planes, padded stride 1024
__device__ float g_prob[NPIX];
__device__ float4 g_reg[NPIX];
__device__ int   g_hist[NBINS];
__device__ int   g_cut;
__device__ int   g_cnt;
__device__ unsigned long long g_cand[CANDMAX];
__device__ float g_box5[KTOP * 5];
__device__ unsigned g_mask0[KTOP * 16];
__device__ unsigned g_mask1[KTOP * 16];
__device__ float g_stage[6632];
__device__ ull   g_stage2[462];
// duplicated {w,w} weights, padded to 10 per (c,o) group
__device__ float4 g_wd2[10 * 16 * 10 / 2];   // 800 float4
__device__ float4 g_wd3[16 * 32 * 10 / 2];   // 2560 float4

// ---------------- packed constant scalars -------
#define OW1 0
#define OB1 270
#define OP1 280
#define OW2 290
#define OB2 1730
#define OP2 1746
#define OW3 1762
#define OB3 6370
#define OP3 6402
#define OWA 6434
#define OBA 6498
#define OWB 6500
#define OBB 6628
#define NCONST 6632
__constant__ float cAll[NCONST];
__constant__ ull cDup[462];   // k1 weights (270), head wa (64), head wb (128)

#define CB1(i) cAll[OB1 + (i)]
#define CP1(i) cAll[OP1 + (i)]
#define CB2(i) cAll[OB2 + (i)]
#define CP2(i) cAll[OP2 + (i)]
#define CB3(i) cAll[OB3 + (i)]
#define CP3(i) cAll[OP3 + (i)]
#define CBA(i) cAll[OBA + (i)]
#define CBB(i) cAll[OBB + (i)]
#define D1(i)  cDup[(i)]
#define DWA(i) cDup[270 + (i)]
#define DWB(i) cDup[334 + (i)]

// ---------------- f32x2 helpers ----------------
__device__ __forceinline__ ull pk2(float lo, float hi) {
    ull r; asm("mov.b64 %0, {%1, %2};" : "=l"(r) : "f"(lo), "f"(hi)); return r;
}
__device__ __forceinline__ void up2(float& lo, float& hi, ull v) {
    asm("mov.b64 {%0, %1}, %2;" : "=f"(lo), "=f"(hi) : "l"(v));
}
__device__ __forceinline__ void ffma2(ull& d, ull a, ull b) {
    asm("fma.rn.f32x2 %0, %1, %2, %0;" : "+l"(d) : "l"(a), "l"(b));
}

// ============ KP: pack weights ============
__global__ void kpack(const float* w1, const float* b1, const float* p1,
                      const float* w2, const float* b2, const float* p2,
                      const float* w3, const float* b3, const float* p3,
                      const float* wa, const float* ba,
                      const float* wb, const float* bb) {
    int t = threadIdx.x;
    for (int i = t; i < 270; i += 256) g_stage[OW1 + i] = w1[i];
    if (t < 10) g_stage[OB1 + t] = b1[t];
    if (t < 10) g_stage[OP1 + t] = p1[t];
    for (int i = t; i < 1440; i += 256) g_stage[OW2 + i] = w2[i];
    if (t < 16) g_stage[OB2 + t] = b2[t];
    if (t < 16) g_stage[OP2 + t] = p2[t];
    for (int i = t; i < 4608; i += 256) g_stage[OW3 + i] = w3[i];
    if (t < 32) g_stage[OB3 + t] = b3[t];
    if (t < 32) g_stage[OP3 + t] = p3[t];
    if (t < 64) g_stage[OWA + t] = wa[t];
    if (t < 2)  g_stage[OBA + t] = ba[t];
    for (int i = t; i < 128; i += 256) g_stage[OWB + i] = wb[i];
    if (t < 4)  g_stage[OBB + t] = bb[t];

    for (int i = t; i < 270; i += 256) {
        unsigned u = __float_as_uint(w1[i]);
        g_stage2[i] = ((ull)u << 32) | u;
    }
    if (t < 64) {
        unsigned u = __float_as_uint(wa[t]);
        g_stage2[270 + t] = ((ull)u << 32) | u;
    }
    for (int i = t; i < 128; i += 256) {
        unsigned u = __float_as_uint(wb[i]);
        g_stage2[334 + i] = ((ull)u << 32) | u;
    }

    // k2: wd2[(c*16+o)*10 + k] = {w,w}
    float* d2 = (float*)g_wd2;
    for (int idx = t; idx < 1440; idx += 256) {
        int k = idx % 9, rest = idx / 9;
        int o = rest % 16, c = rest / 16;
        float w = w2[o * 90 + c * 9 + k];
        int g = (c * 16 + o) * 10 + k;
        d2[g * 2] = w; d2[g * 2 + 1] = w;
    }
    for (int g = t; g < 160; g += 256) {
        d2[(g * 10 + 9) * 2] = 0.f; d2[(g * 10 + 9) * 2 + 1] = 0.f;
    }
    // k3: wd3[(c*32+o)*10 + k] = {w,w}
    float* d3 = (float*)g_wd3;
    for (int idx = t; idx < 4608; idx += 256) {
        int k = idx % 9, rest = idx / 9;
        int o = rest % 32, c = rest / 32;
        float w = w3[o * 144 + c * 9 + k];
        int g = (c * 32 + o) * 10 + k;
        d3[g * 2] = w; d3[g * 2 + 1] = w;
    }
    for (int g = t; g < 512; g += 256) {
        d3[(g * 10 + 9) * 2] = 0.f; d3[(g * 10 + 9) * 2 + 1] = 0.f;
    }
}

// ============ K1: conv1(3->10,3x3) + PReLU + maxpool2, f32x2 ============
__global__ __launch_bounds__(256) void k1(const float* __restrict__ x) {
    int j = blockIdx.x * 16 + threadIdx.x;
    int i = blockIdx.y * 16 + threadIdx.y;
    if (i >= P1 || j >= P1) return;

    ull a01[10], a23[10];
#pragma unroll
    for (int co = 0; co < 10; co++) {
        float b = CB1(co);
        a01[co] = pk2(b, b);
        a23[co] = pk2(b, b);
    }

#pragma unroll
    for (int c = 0; c < 3; c++) {
        const float* xp = x + c * H_IN * W_IN + (2 * i) * W_IN + 2 * j;
        ull t2[4][3];
#pragma unroll
        for (int a = 0; a < 4; a++) {
            const float2* rp = reinterpret_cast<const float2*>(xp + a * W_IN);
            float2 u = rp[0], v = rp[1];
            t2[a][0] = pk2(u.x, u.y);
            t2[a][1] = pk2(u.y, v.x);
            t2[a][2] = pk2(v.x, v.y);
        }
#pragma unroll
        for (int co = 0; co < 10; co++)
#pragma unroll
            for (int dy = 0; dy < 3; dy++)
#pragma unroll
                for (int dx = 0; dx < 3; dx++) {
                    ull w = D1(((co * 3 + c) * 3 + dy) * 3 + dx);
                    ffma2(a01[co], t2[dy][dx], w);
                    ffma2(a23[co], t2[dy + 1][dx], w);
                }
    }

#pragma unroll
    for (int co = 0; co < 10; co++) {
        float a00, a01v, a10, a11;
        up2(a00, a01v, a01[co]);
        up2(a10, a11, a23[co]);
        float al = CP1(co);
        a00  = (a00  >= 0.f) ? a00  : al * a00;
        a01v = (a01v >= 0.f) ? a01v : al * a01v;
        a10  = (a10  >= 0.f) ? a10  : al * a10;
        a11  = (a11  >= 0.f) ? a11  : al * a11;
        g_pool1[co * P1 * P1 + i * P1 + j] = fmaxf(fmaxf(a00, a01v), fmaxf(a10, a11));
    }
}

// ============ K2: conv2(10->16) + PReLU, 4 px/thread, 128-thr blocks ======
#define K2_TW 36
#define K2_DATA (10 * 18 * K2_TW)
#define K2_SMEM_BYTES (K2_DATA * 4 + 10 * 16 * 10 * 8)

__global__ __launch_bounds__(128, 4) void k2() {
    extern __shared__ float dy2[];
    float (*s)[18][K2_TW] = (float(*)[18][K2_TW])dy2;
    ull* wsm = (ull*)(dy2 + K2_DATA);

    int tx = threadIdx.x, ty = threadIdx.y;       // 8 x 16
    int tid = ty * 8 + tx;
    int ox0 = blockIdx.x * 32, oy0 = blockIdx.y * 16;

    {
        float4* wv = (float4*)wsm;
        for (int i = tid; i < 800; i += 128) wv[i] = g_wd2[i];
    }
    for (int idx = tid; idx < 10 * 18 * 34; idx += 128) {
        int c = idx / (18 * 34);
        int rem = idx - c * (18 * 34);
        int r = rem / 34;
        int cc = rem - r * 34;
        int gy = oy0 + r, gx = ox0 + cc;
        s[c][r][cc] = (gy < P1 && gx < P1) ? g_pool1[c * P1 * P1 + gy * P1 + gx] : 0.f;
    }
    __syncthreads();

    int ox = ox0 + tx * 4, oy = oy0 + ty;

    ull accA[16], accB[16];
#pragma unroll
    for (int o = 0; o < 16; o++) {
        float b = CB2(o);
        accA[o] = pk2(b, b);
        accB[o] = pk2(b, b);
    }

#pragma unroll 1
    for (int c = 0; c < 10; c++) {
        ull q[3][5];
#pragma unroll
        for (int r = 0; r < 3; r++) {
            const float* row = &s[c][ty + r][tx * 4];
            float4 A = *reinterpret_cast<const float4*>(row);
            float2 B = *reinterpret_cast<const float2*>(row + 4);
            q[r][0] = pk2(A.x, A.y);
            q[r][1] = pk2(A.y, A.z);
            q[r][2] = pk2(A.z, A.w);
            q[r][3] = pk2(A.w, B.x);
            q[r][4] = pk2(B.x, B.y);
        }
        const ull* wc = wsm + c * 160;
#pragma unroll
        for (int o = 0; o < 16; o++) {
            const ull* w = wc + o * 10;
            ulonglong2 p0 = *(const ulonglong2*)(w + 0);
            ulonglong2 p1 = *(const ulonglong2*)(w + 2);
            ulonglong2 p2 = *(const ulonglong2*)(w + 4);
            ulonglong2 p3 = *(const ulonglong2*)(w + 6);
            ull p8 = w[8];
            ffma2(accA[o], q[0][0], p0.x); ffma2(accB[o], q[0][2], p0.x);
            ffma2(accA[o], q[0][1], p0.y); ffma2(accB[o], q[0][3], p0.y);
            ffma2(accA[o], q[0][2], p1.x); ffma2(accB[o], q[0][4], p1.x);
            ffma2(accA[o], q[1][0], p1.y); ffma2(accB[o], q[1][2], p1.y);
            ffma2(accA[o], q[1][1], p2.x); ffma2(accB[o], q[1][3], p2.x);
            ffma2(accA[o], q[1][2], p2.y); ffma2(accB[o], q[1][4], p2.y);
            ffma2(accA[o], q[2][0], p3.x); ffma2(accB[o], q[2][2], p3.x);
            ffma2(accA[o], q[2][1], p3.y); ffma2(accB[o], q[2][3], p3.y);
            ffma2(accA[o], q[2][2], p8);   ffma2(accB[o], q[2][4], p8);
        }
    }

    if (oy < C2) {
        int base = oy * H2S + ox;
#pragma unroll
        for (int o = 0; o < 16; o++) {
            float v0, v1, v2, v3;
            up2(v0, v1, accA[o]);
            up2(v2, v3, accB[o]);
            float al = CP2(o);
            v0 = (v0 >= 0.f) ? v0 : al * v0;
            v1 = (v1 >= 0.f) ? v1 : al * v1;
            v2 = (v2 >= 0.f) ? v2 : al * v2;
            v3 = (v3 >= 0.f) ? v3 : al * v3;
            float* op = g_h2p + o * (C2 * H2S) + base;
            if (ox + 3 < C2) {
                *reinterpret_cast<float4*>(op) = make_float4(v0, v1, v2, v3);
            } else {
                if (ox < C2)     op[0] = v0;
                if (ox + 1 < C2) op[1] = v1;
                if (ox + 2 < C2) op[2] = v2;
                if (ox + 3 < C2) op[3] = v3;
            }
        }
    }
}

// ============ K3A: conv3(16->32) + PReLU -> g_h3, 8 px/thread ============
#define K3_TILE_F (8 * 18 * 68)               // 9792 floats = 39168 B
#define K3_W_ULL  (8 * 8 * 3 * 4)             // 768 ull = 6144 B
#define K3A_SMEM  (K3_TILE_F * 4 + K3_W_ULL * 8)   // 45312 B

__global__ __launch_bounds__(128, 4) void k3a() {
    extern __shared__ float dyn[];
    float (*s)[18][68] = (float(*)[18][68])dyn;
    ull* wsm = (ull*)(dyn + K3_TILE_F);
    const ull* g_w = (const ull*)g_wd3;

    int tx = threadIdx.x, ty = threadIdx.y;   // (8,16)
    int tid = ty * 8 + tx;
    int ox0 = blockIdx.x * 64, oy0 = blockIdx.y * 16;
    int ox = ox0 + tx * 8, oy = oy0 + ty;

#pragma unroll 1
    for (int og = 0; og < 4; og++) {
        ull acc[8][4];
#pragma unroll
        for (int oo = 0; oo < 8; oo++) {
            float b = CB3(og * 8 + oo);
            ull bb = pk2(b, b);
            acc[oo][0] = bb; acc[oo][1] = bb; acc[oo][2] = bb; acc[oo][3] = bb;
        }

#pragma unroll 1
        for (int cg = 0; cg < 2; cg++) {
            __syncthreads();
            // stage weights for (og, cg): wsm[((c*8+o)*3 + r)*4 + k]
            for (int i = tid; i < K3_W_ULL; i += 128) {
                int k = i & 3;
                int grp = i >> 2;              // (c*8+o)*3 + r
                int r = grp % 3;
                int co = grp / 3;
                int c = co >> 3, o = co & 7;
                ull v = 0;
                if (k < 3)
                    v = g_w[((cg * 8 + c) * 32 + og * 8 + o) * 10 + r * 3 + k];
                wsm[i] = v;
            }
            // stage tile: 8 ch x 18 rows x 33 float2 (66 cols)
            for (int idx = tid; idx < 8 * 18 * 33; idx += 128) {
                int c = idx / 594;
                int rem = idx - c * 594;
                int r = rem / 33;
                int j = rem - r * 33;
                int gy = oy0 + r, gx = ox0 + 2 * j;
                float2 val = make_float2(0.f, 0.f);
                if (gy < C2) {
                    const float* p = &g_h2p[(cg * 8 + c) * (C2 * H2S) + gy * H2S + gx];
                    if (gx + 1 < C2) val = *reinterpret_cast<const float2*>(p);
                    else if (gx < C2) val.x = *p;
                }
                *reinterpret_cast<float2*>(&s[c][r][2 * j]) = val;
            }
            __syncthreads();

#pragma unroll 1
            for (int c = 0; c < 8; c++) {
#pragma unroll
                for (int r = 0; r < 3; r++) {
                    const float* row = &s[c][ty + r][tx * 8];
                    float4 A = *reinterpret_cast<const float4*>(row);
                    float4 B = *reinterpret_cast<const float4*>(row + 4);
                    float2 Cc = *reinterpret_cast<const float2*>(row + 8);
                    ull t0 = pk2(A.x, A.y), t1 = pk2(A.y, A.z), t2 = pk2(A.z, A.w);
                    ull t3 = pk2(A.w, B.x), t4 = pk2(B.x, B.y), t5 = pk2(B.y, B.z);
                    ull t6 = pk2(B.z, B.w), t7 = pk2(B.w, Cc.x), t8 = pk2(Cc.x, Cc.y);
#pragma unroll
                    for (int o = 0; o < 8; o++) {
                        const ull* w = wsm + ((c * 8 + o) * 3 + r) * 4;
                        ulonglong2 w01 = *reinterpret_cast<const ulonglong2*>(w);
                        ull w2 = w[2];
                        ffma2(acc[o][0], t0, w01.x); ffma2(acc[o][0], t1, w01.y); ffma2(acc[o][0], t2, w2);
                        ffma2(acc[o][1], t2, w01.x); ffma2(acc[o][1], t3, w01.y); ffma2(acc[o][1], t4, w2);
                        ffma2(acc[o][2], t4, w01.x); ffma2(acc[o][2], t5, w01.y); ffma2(acc[o][2], t6, w2);
                        ffma2(acc[o][3], t6, w01.x); ffma2(acc[o][3], t7, w01.y); ffma2(acc[o][3], t8, w2);
                    }
                }
            }
        }

        // epilogue for this og: PReLU + store 8 px per o
        if (oy < C3) {
#pragma unroll
            for (int oo = 0; oo < 8; oo++) {
                int o = og * 8 + oo;
                float al = CP3(o);
                float v0, v1, v2, v3, v4, v5, v6, v7;
                up2(v0, v1, acc[oo][0]);
                up2(v2, v3, acc[oo][1]);
                up2(v4, v5, acc[oo][2]);
                up2(v6, v7, acc[oo][3]);
                v0 = (v0 >= 0.f) ? v0 : al * v0;
                v1 = (v1 >= 0.f) ? v1 : al * v1;
                v2 = (v2 >= 0.f) ? v2 : al * v2;
                v3 = (v3 >= 0.f) ? v3 : al * v3;
                v4 = (v4 >= 0.f) ? v4 : al * v4;
                v5 = (v5 >= 0.f) ? v5 : al * v5;
                v6 = (v6 >= 0.f) ? v6 : al * v6;
                v7 = (v7 >= 0.f) ? v7 : al * v7;
                float* op = g_h3 + o * PLANE + oy * 1024 + ox;
                *reinterpret_cast<float4*>(op)     = make_float4(v0, v1, v2, v3);
                *reinterpret_cast<float4*>(op + 4) = make_float4(v4, v5, v6, v7);
            }
        }
    }
}

// ============ KHEAD: 1x1 heads + softmax + hist from g_h3 ============
__global__ __launch_bounds__(256) void khead() {
    int y = blockIdx.x;            // 0..C3-1
    int x = threadIdx.x * 4;       // 0..1020
    const float* base = g_h3 + y * 1024 + x;

    ull hacc[12];
    {
        float b0 = CBA(0), b1 = CBA(1);
        hacc[0] = pk2(b0, b0); hacc[1] = pk2(b0, b0);
        hacc[2] = pk2(b1, b1); hacc[3] = pk2(b1, b1);
#pragma unroll
        for (int qq = 0; qq < 4; qq++) {
            float b = CBB(qq);
            hacc[4 + qq * 2] = pk2(b, b);
            hacc[5 + qq * 2] = pk2(b, b);
        }
    }

#pragma unroll
    for (int o = 0; o < 32; o++) {
        float4 v = *reinterpret_cast<const float4*>(base + o * PLANE);
        ull p01 = pk2(v.x, v.y), p23 = pk2(v.z, v.w);
        ull wa0 = DWA(o), wa1 = DWA(32 + o);
        ffma2(hacc[0], p01, wa0); ffma2(hacc[1], p23, wa0);
        ffma2(hacc[2], p01, wa1); ffma2(hacc[3], p23, wa1);
#pragma unroll
        for (int qq = 0; qq < 4; qq++) {
            ull wq = DWB(qq * 32 + o);
            ffma2(hacc[4 + qq * 2], p01, wq);
            ffma2(hacc[5 + qq * 2], p23, wq);
        }
    }

    float c0v[4], c1v[4], rv[4][4];
    up2(c0v[0], c0v[1], hacc[0]); up2(c0v[2], c0v[3], hacc[1]);
    up2(c1v[0], c1v[1], hacc[2]); up2(c1v[2], c1v[3], hacc[3]);
#pragma unroll
    for (int qq = 0; qq < 4; qq++) {
        up2(rv[qq][0], rv[qq][1], hacc[4 + qq * 2]);
        up2(rv[qq][2], rv[qq][3], hacc[5 + qq * 2]);
    }

#pragma unroll
    for (int px = 0; px < 4; px++) {
        int xx = x + px;
        if (xx >= C3) break;
        float c0 = c0v[px], c1 = c1v[px];
        float mx = fmaxf(c0, c1);
        float e0 = expf(c0 - mx), e1 = expf(c1 - mx);
        float pr = e1 / (e0 + e1);

        int pix = y * C3 + xx;
        g_prob[pix] = pr;
        g_reg[pix] = make_float4(rv[0][px], rv[1][px], rv[2][px], rv[3][px]);

        if (pr >= 0.6f) {
            int bin = (int)((pr - 0.6f) * 20480.f);
            if (bin > NBINS - 1) bin = NBINS - 1;
            atomicAdd(&g_hist[bin], 1);
        }
    }
}

// ============ KH: find histogram cutoff bin ============
__global__ void kh() {
    __shared__ int csum[256];
    int t = threadIdx.x;
    int sum = 0;
    for (int b = t * 32; b < t * 32 + 32; b++) sum += g_hist[b];
    csum[t] = sum;
    __syncthreads();
    int chunk = sum;
    for (int off = 1; off < 256; off <<= 1) {
        int v = csum[t] + ((t + off < 256) ? csum[t + off] : 0);
        __syncthreads();
        csum[t] = v;
        __syncthreads();
    }
    int total = csum[0];
    if (t == 0 && total < KTOP) g_cut = 0;
    int suf_excl = (t < 255) ? csum[t + 1] : 0;
    if (suf_excl < KTOP && suf_excl + chunk >= KTOP) {
        int s = suf_excl;
        int B = t * 32;
        for (int b = t * 32 + 31; b >= t * 32; b--) {
            s += g_hist[b];
            if (s >= KTOP) { B = b; break; }
        }
        g_cut = B;
    }
}

// ============ KC: compact candidates >= cutoff bin ============
__global__ void kc() {
    int i = blockIdx.x * 256 + threadIdx.x;
    if (i >= NPIX) return;
    float pr = g_prob[i];
    if (pr < 0.6f) return;
    int bin = (int)((pr - 0.6f) * 20480.f);
    if (bin > NBINS - 1) bin = NBINS - 1;
    if (bin < g_cut) return;
    int pos = atomicAdd(&g_cnt, 1);
    if (pos < CANDMAX) {
        unsigned long long key =
            ((unsigned long long)__float_as_uint(pr) << 32) |
            (unsigned long long)(~(unsigned)i);
        g_cand[pos] = key;
    }
}

// ============ KS: bitonic sort desc + decode boxes ============
__global__ void ks() {
    __shared__ unsigned long long a[CANDMAX];
    int tid = threadIdx.x;
    int cnt = g_cnt;
    if (cnt > CANDMAX) cnt = CANDMAX;
    for (int i = tid; i < CANDMAX; i += 1024) a[i] = (i < cnt) ? g_cand[i] : 0ULL;
    __syncthreads();

    for (int k = 2; k <= CANDMAX; k <<= 1) {
        for (int j = k >> 1; j > 0; j >>= 1) {
            for (int i = tid; i < CANDMAX; i += 1024) {
                int ixj = i ^ j;
                if (ixj > i) {
                    unsigned long long A = a[i], B = a[ixj];
                    bool desc = ((i & k) == 0);
                    if (desc ? (A < B) : (A > B)) { a[i] = B; a[ixj] = A; }
                }
            }
            __syncthreads();
        }
    }

    if (tid < KTOP) {
        unsigned long long key = a[tid];
        unsigned sb = (unsigned)(key >> 32);
        float sc = sb ? __uint_as_float(sb) : -1.0f;
        float x1 = 0.f, y1 = 0.f, x2 = 0.f, y2 = 0.f;
        if (sc >= 0.6f) {
            unsigned idx = ~(unsigned)(key & 0xFFFFFFFFu);
            float4 rg = g_reg[idx];
            float yy = (float)(idx / C3);
            float xx = (float)(idx % C3);
            float cx = (xx * 2.0f + 6.0f) / 0.6f;
            float cy = (yy * 2.0f + 6.0f) / 0.6f;
            const float ww = 12.0f / 0.6f;
            x1 = cx - ww * 0.5f + rg.x * ww;
            y1 = cy - ww * 0.5f + rg.y * ww;
            x2 = cx + ww * 0.5f + rg.z * ww;
            y2 = cy + ww * 0.5f + rg.w * ww;
        }
        g_box5[tid * 5 + 0] = x1;
        g_box5[tid * 5 + 1] = y1;
        g_box5[tid * 5 + 2] = x2;
        g_box5[tid * 5 + 3] = y2;
        g_box5[tid * 5 + 4] = sc;
    }
}

// ============ KM: build suppression bitmasks ============
__global__ void kmask() {
    int i = blockIdx.x;
    int t = threadIdx.x;
    float ax1 = g_box5[i * 5 + 0], ay1 = g_box5[i * 5 + 1];
    float ax2 = g_box5[i * 5 + 2], ay2 = g_box5[i * 5 + 3];
    float bx1 = g_box5[t * 5 + 0], by1 = g_box5[t * 5 + 1];
    float bx2 = g_box5[t * 5 + 2], by2 = g_box5[t * 5 + 3];
    float aar = (ax2 - ax1) * (ay2 - ay1);
    float bar = (bx2 - bx1) * (by2 - by1);
    float xi1 = fmaxf(ax1, bx1), yi1 = fmaxf(ay1, by1);
    float xi2 = fminf(ax2, bx2), yi2 = fminf(ay2, by2);
    float inter = fmaxf(xi2 - xi1, 0.f) * fmaxf(yi2 - yi1, 0.f);
    float iou = inter / (aar + bar - inter + 1e-9f);
    bool gt = (t > i);
    unsigned b0 = __ballot_sync(0xFFFFFFFFu, gt && (iou > 0.5f));
    unsigned b1 = __ballot_sync(0xFFFFFFFFu, gt && (iou > 0.7f));
    if ((t & 31) == 0) {
        g_mask0[i * 16 + (t >> 5)] = b0;
        g_mask1[i * 16 + (t >> 5)] = b1;
    }
}

// ============ KQ: sequential keep-propagation + output ============
__global__ void kseq(float* __restrict__ out) {
    __shared__ unsigned sm[KTOP * 16];
    __shared__ unsigned skw[16];
    int t = threadIdx.x;
    float x1 = g_box5[t * 5 + 0];
    float y1 = g_box5[t * 5 + 1];
    float x2 = g_box5[t * 5 + 2];
    float y2 = g_box5[t * 5 + 3];
    float sc = g_box5[t * 5 + 4];
    unsigned bal = __ballot_sync(0xFFFFFFFFu, sc >= 0.6f);
    if ((t & 31) == 0) skw[t >> 5] = bal;

    for (int pass = 0; pass < 2; pass++) {
        const unsigned* gm = pass ? g_mask1 : g_mask0;
        for (int i = t; i < KTOP * 16; i += 512) sm[i] = gm[i];
        __syncthreads();
        if (t < 32) {
            unsigned k = (t < 16) ? skw[t] : 0u;
            for (int w = 0; w < 16; w++) {
                unsigned done = 0;
                while (true) {
                    unsigned cur = __shfl_sync(0xFFFFFFFFu, k, w) & ~done;
                    if (!cur) break;
                    int b = __ffs(cur) - 1;
                    done |= (1u << b);
                    int i = w * 32 + b;
                    unsigned m = (t < 16) ? sm[i * 16 + t] : 0u;
                    k &= ~m;
                }
            }
            if (t < 16) skw[t] = k;
        }
        __syncthreads();
    }

    float m = ((skw[t >> 5] >> (t & 31)) & 1u) ? 1.f : 0.f;
    out[t * 5 + 0] = x1 * m;
    out[t * 5 + 1] = y1 * m;
    out[t * 5 + 2] = x2 * m;
    out[t * 5 + 3] = y2 * m;
    out[t * 5 + 4] = sc * m;
}

// ---------------- host launcher ----------------
extern "C" void kernel_launch(void* const* d_in, const int* in_sizes, int n_in,
                              void* d_out, int out_size) {
    const float* x = (const float*)d_in[0];

    kpack<<<1, 256>>>((const float*)d_in[1], (const float*)d_in[2], (const float*)d_in[3],
                      (const float*)d_in[4], (const float*)d_in[5], (const float*)d_in[6],
                      (const float*)d_in[7], (const float*)d_in[8], (const float*)d_in[9],
                      (const float*)d_in[10], (const float*)d_in[11],
                      (const float*)d_in[12], (const float*)d_in[13]);

    void* sp = 0; cudaGetSymbolAddress(&sp, g_stage);
    cudaMemcpyToSymbolAsync(cAll, sp, NCONST * sizeof(float), 0, cudaMemcpyDeviceToDevice);
    void* sp2 = 0; cudaGetSymbolAddress(&sp2, g_stage2);
    cudaMemcpyToSymbolAsync(cDup, sp2, 462 * sizeof(ull), 0, cudaMemcpyDeviceToDevice);

    void* hp = 0; cudaGetSymbolAddress(&hp, g_hist);
    cudaMemsetAsync(hp, 0, NBINS * sizeof(int));
    void* cp = 0; cudaGetSymbolAddress(&cp, g_cnt);
    cudaMemsetAsync(cp, 0, sizeof(int));

    cudaFuncSetAttribute(k2, cudaFuncAttributeMaxDynamicSharedMemorySize, K2_SMEM_BYTES);
    cudaFuncSetAttribute(k3a, cudaFuncAttributeMaxDynamicSharedMemorySize, K3A_SMEM);

    k1<<<dim3(64, 64), dim3(16, 16)>>>(x);
    k2<<<dim3(32, 64), dim3(8, 16), K2_SMEM_BYTES>>>();
    k3a<<<dim3(16, 64), dim3(8, 16), K3A_SMEM>>>();
    khead<<<C3, 256>>>();
    kh<<<1, 256>>>();
    kc<<<(NPIX + 255) / 256, 256>>>();
    ks<<<1, 1024>>>();
    kmask<<<KTOP, KTOP>>>();
    kseq<<<1, 512>>>((float*)d_out);
}

// round 9
// speedup vs baseline: 1.1977x; 1.1977x over previous
#include <cuda_runtime.h>
#include <math.h>
#include <stdint.h>

// ---------------- problem constants ----------------
#define H_IN 2048
#define W_IN 2048
#define P1   1023            // after conv1(2046) + maxpool2
#define C2   1021            // after conv2
#define H2S  1024            // padded row stride for h2
#define C3   1019            // after conv3
#define NPIX (C3*C3)         // 1038361
#define NBINS 8192
#define CANDMAX 4096
#define KTOP 512

typedef unsigned long long ull;

// ---------------- scratch (device globals) ----------
__device__ float g_pool1[10 * P1 * P1];
__device__ float g_h2p[16 * C2 * H2S];      // padded stride 1024
__device__ float g_prob[NPIX];
__device__ float4 g_reg[NPIX];
__device__ int   g_hist[NBINS];
__device__ int   g_cut;
__device__ int   g_cnt;
__device__ unsigned long long g_cand[CANDMAX];
__device__ float g_box5[KTOP * 5];
__device__ unsigned g_mask0[KTOP * 16];
__device__ unsigned g_mask1[KTOP * 16];
__device__ float g_stage[6632];
__device__ ull   g_stage2[462];
// duplicated {w,w} weights, padded to 10 per (c,o) group
__device__ float4 g_wd2[10 * 16 * 10 / 2];   // 800 float4
__device__ float4 g_wd3[16 * 32 * 10 / 2];   // 2560 float4

// ---------------- packed constant scalars -------
#define OW1 0
#define OB1 270
#define OP1 280
#define OW2 290
#define OB2 1730
#define OP2 1746
#define OW3 1762
#define OB3 6370
#define OP3 6402
#define OWA 6434
#define OBA 6498
#define OWB 6500
#define OBB 6628
#define NCONST 6632
__constant__ float cAll[NCONST];
__constant__ ull cDup[462];   // k1 weights (270), head wa (64), head wb (128)

#define CB1(i) cAll[OB1 + (i)]
#define CP1(i) cAll[OP1 + (i)]
#define CB2(i) cAll[OB2 + (i)]
#define CP2(i) cAll[OP2 + (i)]
#define CB3(i) cAll[OB3 + (i)]
#define CP3(i) cAll[OP3 + (i)]
#define CBA(i) cAll[OBA + (i)]
#define CBB(i) cAll[OBB + (i)]
#define D1(i)  cDup[(i)]
#define DWA(i) cDup[270 + (i)]
#define DWB(i) cDup[334 + (i)]

// ---------------- f32x2 helpers ----------------
__device__ __forceinline__ ull pk2(float lo, float hi) {
    ull r; asm("mov.b64 %0, {%1, %2};" : "=l"(r) : "f"(lo), "f"(hi)); return r;
}
__device__ __forceinline__ void up2(float& lo, float& hi, ull v) {
    asm("mov.b64 {%0, %1}, %2;" : "=f"(lo), "=f"(hi) : "l"(v));
}
__device__ __forceinline__ void ffma2(ull& d, ull a, ull b) {
    asm("fma.rn.f32x2 %0, %1, %2, %0;" : "+l"(d) : "l"(a), "l"(b));
}

// ============ KP: pack weights ============
__global__ void kpack(const float* w1, const float* b1, const float* p1,
                      const float* w2, const float* b2, const float* p2,
                      const float* w3, const float* b3, const float* p3,
                      const float* wa, const float* ba,
                      const float* wb, const float* bb) {
    int t = threadIdx.x;
    for (int i = t; i < 270; i += 256) g_stage[OW1 + i] = w1[i];
    if (t < 10) g_stage[OB1 + t] = b1[t];
    if (t < 10) g_stage[OP1 + t] = p1[t];
    for (int i = t; i < 1440; i += 256) g_stage[OW2 + i] = w2[i];
    if (t < 16) g_stage[OB2 + t] = b2[t];
    if (t < 16) g_stage[OP2 + t] = p2[t];
    for (int i = t; i < 4608; i += 256) g_stage[OW3 + i] = w3[i];
    if (t < 32) g_stage[OB3 + t] = b3[t];
    if (t < 32) g_stage[OP3 + t] = p3[t];
    if (t < 64) g_stage[OWA + t] = wa[t];
    if (t < 2)  g_stage[OBA + t] = ba[t];
    for (int i = t; i < 128; i += 256) g_stage[OWB + i] = wb[i];
    if (t < 4)  g_stage[OBB + t] = bb[t];

    for (int i = t; i < 270; i += 256) {
        unsigned u = __float_as_uint(w1[i]);
        g_stage2[i] = ((ull)u << 32) | u;
    }
    if (t < 64) {
        unsigned u = __float_as_uint(wa[t]);
        g_stage2[270 + t] = ((ull)u << 32) | u;
    }
    for (int i = t; i < 128; i += 256) {
        unsigned u = __float_as_uint(wb[i]);
        g_stage2[334 + i] = ((ull)u << 32) | u;
    }

    // k2: wd2[(c*16+o)*10 + k] = {w,w}
    float* d2 = (float*)g_wd2;
    for (int idx = t; idx < 1440; idx += 256) {
        int k = idx % 9, rest = idx / 9;
        int o = rest % 16, c = rest / 16;
        float w = w2[o * 90 + c * 9 + k];
        int g = (c * 16 + o) * 10 + k;
        d2[g * 2] = w; d2[g * 2 + 1] = w;
    }
    for (int g = t; g < 160; g += 256) {
        d2[(g * 10 + 9) * 2] = 0.f; d2[(g * 10 + 9) * 2 + 1] = 0.f;
    }
    // k3: wd3[(c*32+o)*10 + k] = {w,w}
    float* d3 = (float*)g_wd3;
    for (int idx = t; idx < 4608; idx += 256) {
        int k = idx % 9, rest = idx / 9;
        int o = rest % 32, c = rest / 32;
        float w = w3[o * 144 + c * 9 + k];
        int g = (c * 32 + o) * 10 + k;
        d3[g * 2] = w; d3[g * 2 + 1] = w;
    }
    for (int g = t; g < 512; g += 256) {
        d3[(g * 10 + 9) * 2] = 0.f; d3[(g * 10 + 9) * 2 + 1] = 0.f;
    }
}

// ============ K1: conv1(3->10,3x3) + PReLU + maxpool2, f32x2 ============
__global__ __launch_bounds__(256) void k1(const float* __restrict__ x) {
    int j = blockIdx.x * 16 + threadIdx.x;
    int i = blockIdx.y * 16 + threadIdx.y;
    if (i >= P1 || j >= P1) return;

    ull a01[10], a23[10];
#pragma unroll
    for (int co = 0; co < 10; co++) {
        float b = CB1(co);
        a01[co] = pk2(b, b);
        a23[co] = pk2(b, b);
    }

#pragma unroll
    for (int c = 0; c < 3; c++) {
        const float* xp = x + c * H_IN * W_IN + (2 * i) * W_IN + 2 * j;
        ull t2[4][3];
#pragma unroll
        for (int a = 0; a < 4; a++) {
            const float2* rp = reinterpret_cast<const float2*>(xp + a * W_IN);
            float2 u = rp[0], v = rp[1];
            t2[a][0] = pk2(u.x, u.y);
            t2[a][1] = pk2(u.y, v.x);
            t2[a][2] = pk2(v.x, v.y);
        }
#pragma unroll
        for (int co = 0; co < 10; co++)
#pragma unroll
            for (int dy = 0; dy < 3; dy++)
#pragma unroll
                for (int dx = 0; dx < 3; dx++) {
                    ull w = D1(((co * 3 + c) * 3 + dy) * 3 + dx);
                    ffma2(a01[co], t2[dy][dx], w);
                    ffma2(a23[co], t2[dy + 1][dx], w);
                }
    }

#pragma unroll
    for (int co = 0; co < 10; co++) {
        float a00, a01v, a10, a11;
        up2(a00, a01v, a01[co]);
        up2(a10, a11, a23[co]);
        float al = CP1(co);
        a00  = (a00  >= 0.f) ? a00  : al * a00;
        a01v = (a01v >= 0.f) ? a01v : al * a01v;
        a10  = (a10  >= 0.f) ? a10  : al * a10;
        a11  = (a11  >= 0.f) ? a11  : al * a11;
        g_pool1[co * P1 * P1 + i * P1 + j] = fmaxf(fmaxf(a00, a01v), fmaxf(a10, a11));
    }
}

// ============ K2: conv2(10->16) + PReLU, 6 px/thread, 8-out halves ======
#define K2_TS 52
#define K2_DATA (10 * 18 * K2_TS)                 // 9360 floats
#define K2_WQ 800                                 // ull per half: 10c x 8oo x 10
#define K2_SMEM_BYTES (K2_DATA * 4 + K2_WQ * 8)   // 37440 + 6400 = 43840

__global__ __launch_bounds__(128, 4) void k2() {
    extern __shared__ float dy2[];
    float (*s)[18][K2_TS] = (float(*)[18][K2_TS])dy2;
    ull* wsm = (ull*)(dy2 + K2_DATA);

    int tx = threadIdx.x, ty = threadIdx.y;       // 8 x 16
    int tid = ty * 8 + tx;
    int ox0 = blockIdx.x * 48, oy0 = blockIdx.y * 16;
    int ox = ox0 + tx * 6, oy = oy0 + ty;

    // stage tile (scalar: g_pool1 rows have odd stride)
    for (int idx = tid; idx < 10 * 18 * 50; idx += 128) {
        int c = idx / 900;
        int rem = idx - c * 900;
        int r = rem / 50;
        int j = rem - r * 50;
        int gy = oy0 + r, gx = ox0 + j;
        s[c][r][j] = (gy < P1 && gx < P1) ? g_pool1[c * P1 * P1 + gy * P1 + gx] : 0.f;
    }

#pragma unroll 1
    for (int og = 0; og < 2; og++) {
        __syncthreads();
        {
            float4* wv = (float4*)wsm;
            for (int i = tid; i < 400; i += 128) {
                int grp = i / 5, k4 = i - grp * 5;
                int c = grp >> 3, oo = grp & 7;
                wv[i] = g_wd2[(c * 16 + og * 8 + oo) * 5 + k4];
            }
        }
        __syncthreads();

        ull acc[8][3];
#pragma unroll
        for (int oo = 0; oo < 8; oo++) {
            float b = CB2(og * 8 + oo);
            ull bb = pk2(b, b);
            acc[oo][0] = bb; acc[oo][1] = bb; acc[oo][2] = bb;
        }

#pragma unroll 1
        for (int c = 0; c < 10; c++) {
            ull t[3][7];
#pragma unroll
            for (int r = 0; r < 3; r++) {
                const float* row = &s[c][ty + r][tx * 6];
                float2 a0 = *reinterpret_cast<const float2*>(row);
                float2 a1 = *reinterpret_cast<const float2*>(row + 2);
                float2 a2 = *reinterpret_cast<const float2*>(row + 4);
                float2 a3 = *reinterpret_cast<const float2*>(row + 6);
                t[r][0] = pk2(a0.x, a0.y); t[r][1] = pk2(a0.y, a1.x);
                t[r][2] = pk2(a1.x, a1.y); t[r][3] = pk2(a1.y, a2.x);
                t[r][4] = pk2(a2.x, a2.y); t[r][5] = pk2(a2.y, a3.x);
                t[r][6] = pk2(a3.x, a3.y);
            }
            const ull* wc = wsm + c * 80;
#pragma unroll
            for (int oo = 0; oo < 8; oo++) {
                const ull* w = wc + oo * 10;
                ulonglong2 p0 = *(const ulonglong2*)(w + 0);
                ulonglong2 p1 = *(const ulonglong2*)(w + 2);
                ulonglong2 p2 = *(const ulonglong2*)(w + 4);
                ulonglong2 p3 = *(const ulonglong2*)(w + 6);
                ull p8 = w[8];
                ffma2(acc[oo][0], t[0][0], p0.x); ffma2(acc[oo][1], t[0][2], p0.x); ffma2(acc[oo][2], t[0][4], p0.x);
                ffma2(acc[oo][0], t[0][1], p0.y); ffma2(acc[oo][1], t[0][3], p0.y); ffma2(acc[oo][2], t[0][5], p0.y);
                ffma2(acc[oo][0], t[0][2], p1.x); ffma2(acc[oo][1], t[0][4], p1.x); ffma2(acc[oo][2], t[0][6], p1.x);
                ffma2(acc[oo][0], t[1][0], p1.y); ffma2(acc[oo][1], t[1][2], p1.y); ffma2(acc[oo][2], t[1][4], p1.y);
                ffma2(acc[oo][0], t[1][1], p2.x); ffma2(acc[oo][1], t[1][3], p2.x); ffma2(acc[oo][2], t[1][5], p2.x);
                ffma2(acc[oo][0], t[1][2], p2.y); ffma2(acc[oo][1], t[1][4], p2.y); ffma2(acc[oo][2], t[1][6], p2.y);
                ffma2(acc[oo][0], t[2][0], p3.x); ffma2(acc[oo][1], t[2][2], p3.x); ffma2(acc[oo][2], t[2][4], p3.x);
                ffma2(acc[oo][0], t[2][1], p3.y); ffma2(acc[oo][1], t[2][3], p3.y); ffma2(acc[oo][2], t[2][5], p3.y);
                ffma2(acc[oo][0], t[2][2], p8);   ffma2(acc[oo][1], t[2][4], p8);   ffma2(acc[oo][2], t[2][6], p8);
            }
        }

        if (oy < C2) {
#pragma unroll
            for (int oo = 0; oo < 8; oo++) {
                int o = og * 8 + oo;
                float al = CP2(o);
                float v0, v1, v2, v3, v4, v5;
                up2(v0, v1, acc[oo][0]);
                up2(v2, v3, acc[oo][1]);
                up2(v4, v5, acc[oo][2]);
                v0 = (v0 >= 0.f) ? v0 : al * v0;
                v1 = (v1 >= 0.f) ? v1 : al * v1;
                v2 = (v2 >= 0.f) ? v2 : al * v2;
                v3 = (v3 >= 0.f) ? v3 : al * v3;
                v4 = (v4 >= 0.f) ? v4 : al * v4;
                v5 = (v5 >= 0.f) ? v5 : al * v5;
                float* op = g_h2p + o * (C2 * H2S) + oy * H2S + ox;
                if (ox + 5 < C2) {
                    *reinterpret_cast<float2*>(op)     = make_float2(v0, v1);
                    *reinterpret_cast<float2*>(op + 2) = make_float2(v2, v3);
                    *reinterpret_cast<float2*>(op + 4) = make_float2(v4, v5);
                } else {
                    if (ox < C2)     op[0] = v0;
                    if (ox + 1 < C2) op[1] = v1;
                    if (ox + 2 < C2) op[2] = v2;
                    if (ox + 3 < C2) op[3] = v3;
                    if (ox + 4 < C2) op[4] = v4;
                    if (ox + 5 < C2) op[5] = v5;
                }
            }
        }
    }
}

// ============ K3: conv3(16->32) + PReLU + heads + softmax + hist =========
//  6 px/thread, 8-output quarters, tile staged once, weights per quarter
#define K3_TS 52
#define K3_DATA (16 * 18 * K3_TS)                 // 14976 floats
#define K3_WQ 1280                                // ull per quarter: 16c x 8oo x 10
#define K3_SMEM_BYTES (K3_DATA * 4 + K3_WQ * 8)   // 59904 + 10240 = 70144

__global__ __launch_bounds__(128, 3) void k3() {
    extern __shared__ float dy3[];
    float (*s)[18][K3_TS] = (float(*)[18][K3_TS])dy3;
    ull* wsm = (ull*)(dy3 + K3_DATA);

    int tx = threadIdx.x, ty = threadIdx.y;       // 8 x 16
    int tid = ty * 8 + tx;
    int ox0 = blockIdx.x * 48, oy0 = blockIdx.y * 16;
    int ox = ox0 + tx * 6, oy = oy0 + ty;

    // stage tile once (float2, g_h2p stride is even)
    for (int idx = tid; idx < 16 * 18 * 25; idx += 128) {
        int c = idx / 450;
        int rem = idx - c * 450;
        int r = rem / 25;
        int j = rem - r * 25;
        int gy = oy0 + r, gx = ox0 + 2 * j;
        float2 v = make_float2(0.f, 0.f);
        if (gy < C2) {
            const float* p = &g_h2p[c * (C2 * H2S) + gy * H2S + gx];
            if (gx + 1 < C2) v = *reinterpret_cast<const float2*>(p);
            else if (gx < C2) v.x = *p;
        }
        *reinterpret_cast<float2*>(&s[c][r][2 * j]) = v;
    }

    // head accumulators: c0,c1,r0..r3, each 3 px-pairs
    ull hacc[18];
    {
        float b0 = CBA(0), b1 = CBA(1);
        ull q0 = pk2(b0, b0), q1 = pk2(b1, b1);
        hacc[0] = q0; hacc[1] = q0; hacc[2] = q0;
        hacc[3] = q1; hacc[4] = q1; hacc[5] = q1;
#pragma unroll
        for (int qq = 0; qq < 4; qq++) {
            float b = CBB(qq);
            ull qb = pk2(b, b);
            hacc[6 + qq * 3 + 0] = qb;
            hacc[6 + qq * 3 + 1] = qb;
            hacc[6 + qq * 3 + 2] = qb;
        }
    }

#pragma unroll 1
    for (int og = 0; og < 4; og++) {
        __syncthreads();
        {
            float4* wv = (float4*)wsm;
            for (int i = tid; i < 640; i += 128) {
                int grp = i / 5, k4 = i - grp * 5;
                int c = grp >> 3, oo = grp & 7;
                wv[i] = g_wd3[(c * 32 + og * 8 + oo) * 5 + k4];
            }
        }
        __syncthreads();

        ull acc[8][3];
#pragma unroll
        for (int oo = 0; oo < 8; oo++) {
            float b = CB3(og * 8 + oo);
            ull bb = pk2(b, b);
            acc[oo][0] = bb; acc[oo][1] = bb; acc[oo][2] = bb;
        }

#pragma unroll 1
        for (int c = 0; c < 16; c++) {
            ull t[3][7];
#pragma unroll
            for (int r = 0; r < 3; r++) {
                const float* row = &s[c][ty + r][tx * 6];
                float2 a0 = *reinterpret_cast<const float2*>(row);
                float2 a1 = *reinterpret_cast<const float2*>(row + 2);
                float2 a2 = *reinterpret_cast<const float2*>(row + 4);
                float2 a3 = *reinterpret_cast<const float2*>(row + 6);
                t[r][0] = pk2(a0.x, a0.y); t[r][1] = pk2(a0.y, a1.x);
                t[r][2] = pk2(a1.x, a1.y); t[r][3] = pk2(a1.y, a2.x);
                t[r][4] = pk2(a2.x, a2.y); t[r][5] = pk2(a2.y, a3.x);
                t[r][6] = pk2(a3.x, a3.y);
            }
            const ull* wc = wsm + c * 80;
#pragma unroll
            for (int oo = 0; oo < 8; oo++) {
                const ull* w = wc + oo * 10;
                ulonglong2 p0 = *(const ulonglong2*)(w + 0);
                ulonglong2 p1 = *(const ulonglong2*)(w + 2);
                ulonglong2 p2 = *(const ulonglong2*)(w + 4);
                ulonglong2 p3 = *(const ulonglong2*)(w + 6);
                ull p8 = w[8];
                ffma2(acc[oo][0], t[0][0], p0.x); ffma2(acc[oo][1], t[0][2], p0.x); ffma2(acc[oo][2], t[0][4], p0.x);
                ffma2(acc[oo][0], t[0][1], p0.y); ffma2(acc[oo][1], t[0][3], p0.y); ffma2(acc[oo][2], t[0][5], p0.y);
                ffma2(acc[oo][0], t[0][2], p1.x); ffma2(acc[oo][1], t[0][4], p1.x); ffma2(acc[oo][2], t[0][6], p1.x);
                ffma2(acc[oo][0], t[1][0], p1.y); ffma2(acc[oo][1], t[1][2], p1.y); ffma2(acc[oo][2], t[1][4], p1.y);
                ffma2(acc[oo][0], t[1][1], p2.x); ffma2(acc[oo][1], t[1][3], p2.x); ffma2(acc[oo][2], t[1][5], p2.x);
                ffma2(acc[oo][0], t[1][2], p2.y); ffma2(acc[oo][1], t[1][4], p2.y); ffma2(acc[oo][2], t[1][6], p2.y);
                ffma2(acc[oo][0], t[2][0], p3.x); ffma2(acc[oo][1], t[2][2], p3.x); ffma2(acc[oo][2], t[2][4], p3.x);
                ffma2(acc[oo][0], t[2][1], p3.y); ffma2(acc[oo][1], t[2][3], p3.y); ffma2(acc[oo][2], t[2][5], p3.y);
                ffma2(acc[oo][0], t[2][2], p8);   ffma2(acc[oo][1], t[2][4], p8);   ffma2(acc[oo][2], t[2][6], p8);
            }
        }

        // PReLU + incremental head accumulation for this quarter
#pragma unroll
        for (int oo = 0; oo < 8; oo++) {
            int o = og * 8 + oo;
            float al = CP3(o);
            float v0, v1, v2, v3, v4, v5;
            up2(v0, v1, acc[oo][0]);
            up2(v2, v3, acc[oo][1]);
            up2(v4, v5, acc[oo][2]);
            v0 = (v0 >= 0.f) ? v0 : al * v0;
            v1 = (v1 >= 0.f) ? v1 : al * v1;
            v2 = (v2 >= 0.f) ? v2 : al * v2;
            v3 = (v3 >= 0.f) ? v3 : al * v3;
            v4 = (v4 >= 0.f) ? v4 : al * v4;
            v5 = (v5 >= 0.f) ? v5 : al * v5;
            ull pA = pk2(v0, v1), pB = pk2(v2, v3), pC = pk2(v4, v5);
            ull wa0 = DWA(o), wa1 = DWA(32 + o);
            ffma2(hacc[0], pA, wa0); ffma2(hacc[1], pB, wa0); ffma2(hacc[2], pC, wa0);
            ffma2(hacc[3], pA, wa1); ffma2(hacc[4], pB, wa1); ffma2(hacc[5], pC, wa1);
#pragma unroll
            for (int qq = 0; qq < 4; qq++) {
                ull wq = DWB(qq * 32 + o);
                ffma2(hacc[6 + qq * 3 + 0], pA, wq);
                ffma2(hacc[6 + qq * 3 + 1], pB, wq);
                ffma2(hacc[6 + qq * 3 + 2], pC, wq);
            }
        }
    }

    if (oy >= C3) return;

    float c0v[6], c1v[6], rv[4][6];
    up2(c0v[0], c0v[1], hacc[0]); up2(c0v[2], c0v[3], hacc[1]); up2(c0v[4], c0v[5], hacc[2]);
    up2(c1v[0], c1v[1], hacc[3]); up2(c1v[2], c1v[3], hacc[4]); up2(c1v[4], c1v[5], hacc[5]);
#pragma unroll
    for (int qq = 0; qq < 4; qq++) {
        up2(rv[qq][0], rv[qq][1], hacc[6 + qq * 3 + 0]);
        up2(rv[qq][2], rv[qq][3], hacc[6 + qq * 3 + 1]);
        up2(rv[qq][4], rv[qq][5], hacc[6 + qq * 3 + 2]);
    }

#pragma unroll
    for (int px = 0; px < 6; px++) {
        int oxx = ox + px;
        if (oxx >= C3) break;
        float c0 = c0v[px], c1 = c1v[px];
        float mx = fmaxf(c0, c1);
        float e0 = expf(c0 - mx), e1 = expf(c1 - mx);
        float pr = e1 / (e0 + e1);

        int pix = oy * C3 + oxx;
        g_prob[pix] = pr;
        g_reg[pix] = make_float4(rv[0][px], rv[1][px], rv[2][px], rv[3][px]);

        if (pr >= 0.6f) {
            int bin = (int)((pr - 0.6f) * 20480.f);
            if (bin > NBINS - 1) bin = NBINS - 1;
            atomicAdd(&g_hist[bin], 1);
        }
    }
}

// ============ KH: find histogram cutoff bin ============
__global__ void kh() {
    __shared__ int csum[256];
    int t = threadIdx.x;
    int sum = 0;
    for (int b = t * 32; b < t * 32 + 32; b++) sum += g_hist[b];
    csum[t] = sum;
    __syncthreads();
    int chunk = sum;
    for (int off = 1; off < 256; off <<= 1) {
        int v = csum[t] + ((t + off < 256) ? csum[t + off] : 0);
        __syncthreads();
        csum[t] = v;
        __syncthreads();
    }
    int total = csum[0];
    if (t == 0 && total < KTOP) g_cut = 0;
    int suf_excl = (t < 255) ? csum[t + 1] : 0;
    if (suf_excl < KTOP && suf_excl + chunk >= KTOP) {
        int s = suf_excl;
        int B = t * 32;
        for (int b = t * 32 + 31; b >= t * 32; b--) {
            s += g_hist[b];
            if (s >= KTOP) { B = b; break; }
        }
        g_cut = B;
    }
}

// ============ KC: compact candidates >= cutoff bin ============
__global__ void kc() {
    int i = blockIdx.x * 256 + threadIdx.x;
    if (i >= NPIX) return;
    float pr = g_prob[i];
    if (pr < 0.6f) return;
    int bin = (int)((pr - 0.6f) * 20480.f);
    if (bin > NBINS - 1) bin = NBINS - 1;
    if (bin < g_cut) return;
    int pos = atomicAdd(&g_cnt, 1);
    if (pos < CANDMAX) {
        unsigned long long key =
            ((unsigned long long)__float_as_uint(pr) << 32) |
            (unsigned long long)(~(unsigned)i);
        g_cand[pos] = key;
    }
}

// ============ KS: bitonic sort desc + decode boxes ============
__global__ void ks() {
    __shared__ unsigned long long a[CANDMAX];
    int tid = threadIdx.x;
    int cnt = g_cnt;
    if (cnt > CANDMAX) cnt = CANDMAX;
    for (int i = tid; i < CANDMAX; i += 1024) a[i] = (i < cnt) ? g_cand[i] : 0ULL;
    __syncthreads();

    for (int k = 2; k <= CANDMAX; k <<= 1) {
        for (int j = k >> 1; j > 0; j >>= 1) {
            for (int i = tid; i < CANDMAX; i += 1024) {
                int ixj = i ^ j;
                if (ixj > i) {
                    unsigned long long A = a[i], B = a[ixj];
                    bool desc = ((i & k) == 0);
                    if (desc ? (A < B) : (A > B)) { a[i] = B; a[ixj] = A; }
                }
            }
            __syncthreads();
        }
    }

    if (tid < KTOP) {
        unsigned long long key = a[tid];
        unsigned sb = (unsigned)(key >> 32);
        float sc = sb ? __uint_as_float(sb) : -1.0f;
        float x1 = 0.f, y1 = 0.f, x2 = 0.f, y2 = 0.f;
        if (sc >= 0.6f) {
            unsigned idx = ~(unsigned)(key & 0xFFFFFFFFu);
            float4 rg = g_reg[idx];
            float yy = (float)(idx / C3);
            float xx = (float)(idx % C3);
            float cx = (xx * 2.0f + 6.0f) / 0.6f;
            float cy = (yy * 2.0f + 6.0f) / 0.6f;
            const float ww = 12.0f / 0.6f;
            x1 = cx - ww * 0.5f + rg.x * ww;
            y1 = cy - ww * 0.5f + rg.y * ww;
            x2 = cx + ww * 0.5f + rg.z * ww;
            y2 = cy + ww * 0.5f + rg.w * ww;
        }
        g_box5[tid * 5 + 0] = x1;
        g_box5[tid * 5 + 1] = y1;
        g_box5[tid * 5 + 2] = x2;
        g_box5[tid * 5 + 3] = y2;
        g_box5[tid * 5 + 4] = sc;
    }
}

// ============ KM: build suppression bitmasks ============
__global__ void kmask() {
    int i = blockIdx.x;
    int t = threadIdx.x;
    float ax1 = g_box5[i * 5 + 0], ay1 = g_box5[i * 5 + 1];
    float ax2 = g_box5[i * 5 + 2], ay2 = g_box5[i * 5 + 3];
    float bx1 = g_box5[t * 5 + 0], by1 = g_box5[t * 5 + 1];
    float bx2 = g_box5[t * 5 + 2], by2 = g_box5[t * 5 + 3];
    float aar = (ax2 - ax1) * (ay2 - ay1);
    float bar = (bx2 - bx1) * (by2 - by1);
    float xi1 = fmaxf(ax1, bx1), yi1 = fmaxf(ay1, by1);
    float xi2 = fminf(ax2, bx2), yi2 = fminf(ay2, by2);
    float inter = fmaxf(xi2 - xi1, 0.f) * fmaxf(yi2 - yi1, 0.f);
    float iou = inter / (aar + bar - inter + 1e-9f);
    bool gt = (t > i);
    unsigned b0 = __ballot_sync(0xFFFFFFFFu, gt && (iou > 0.5f));
    unsigned b1 = __ballot_sync(0xFFFFFFFFu, gt && (iou > 0.7f));
    if ((t & 31) == 0) {
        g_mask0[i * 16 + (t >> 5)] = b0;
        g_mask1[i * 16 + (t >> 5)] = b1;
    }
}

// ============ KQ: sequential keep-propagation + output ============
__global__ void kseq(float* __restrict__ out) {
    __shared__ unsigned sm[KTOP * 16];
    __shared__ unsigned skw[16];
    int t = threadIdx.x;
    float x1 = g_box5[t * 5 + 0];
    float y1 = g_box5[t * 5 + 1];
    float x2 = g_box5[t * 5 + 2];
    float y2 = g_box5[t * 5 + 3];
    float sc = g_box5[t * 5 + 4];
    unsigned bal = __ballot_sync(0xFFFFFFFFu, sc >= 0.6f);
    if ((t & 31) == 0) skw[t >> 5] = bal;

    for (int pass = 0; pass < 2; pass++) {
        const unsigned* gm = pass ? g_mask1 : g_mask0;
        for (int i = t; i < KTOP * 16; i += 512) sm[i] = gm[i];
        __syncthreads();
        if (t < 32) {
            unsigned k = (t < 16) ? skw[t] : 0u;
            for (int w = 0; w < 16; w++) {
                unsigned done = 0;
                while (true) {
                    unsigned cur = __shfl_sync(0xFFFFFFFFu, k, w) & ~done;
                    if (!cur) break;
                    int b = __ffs(cur) - 1;
                    done |= (1u << b);
                    int i = w * 32 + b;
                    unsigned m = (t < 16) ? sm[i * 16 + t] : 0u;
                    k &= ~m;
                }
            }
            if (t < 16) skw[t] = k;
        }
        __syncthreads();
    }

    float m = ((skw[t >> 5] >> (t & 31)) & 1u) ? 1.f : 0.f;
    out[t * 5 + 0] = x1 * m;
    out[t * 5 + 1] = y1 * m;
    out[t * 5 + 2] = x2 * m;
    out[t * 5 + 3] = y2 * m;
    out[t * 5 + 4] = sc * m;
}

// ---------------- host launcher ----------------
extern "C" void kernel_launch(void* const* d_in, const int* in_sizes, int n_in,
                              void* d_out, int out_size) {
    const float* x = (const float*)d_in[0];

    kpack<<<1, 256>>>((const float*)d_in[1], (const float*)d_in[2], (const float*)d_in[3],
                      (const float*)d_in[4], (const float*)d_in[5], (const float*)d_in[6],
                      (const float*)d_in[7], (const float*)d_in[8], (const float*)d_in[9],
                      (const float*)d_in[10], (const float*)d_in[11],
                      (const float*)d_in[12], (const float*)d_in[13]);

    void* sp = 0; cudaGetSymbolAddress(&sp, g_stage);
    cudaMemcpyToSymbolAsync(cAll, sp, NCONST * sizeof(float), 0, cudaMemcpyDeviceToDevice);
    void* sp2 = 0; cudaGetSymbolAddress(&sp2, g_stage2);
    cudaMemcpyToSymbolAsync(cDup, sp2, 462 * sizeof(ull), 0, cudaMemcpyDeviceToDevice);

    void* hp = 0; cudaGetSymbolAddress(&hp, g_hist);
    cudaMemsetAsync(hp, 0, NBINS * sizeof(int));
    void* cp = 0; cudaGetSymbolAddress(&cp, g_cnt);
    cudaMemsetAsync(cp, 0, sizeof(int));

    cudaFuncSetAttribute(k2, cudaFuncAttributeMaxDynamicSharedMemorySize, K2_SMEM_BYTES);
    cudaFuncSetAttribute(k3, cudaFuncAttributeMaxDynamicSharedMemorySize, K3_SMEM_BYTES);

    k1<<<dim3(64, 64), dim3(16, 16)>>>(x);
    k2<<<dim3(22, 64), dim3(8, 16), K2_SMEM_BYTES>>>();
    k3<<<dim3(22, 64), dim3(8, 16), K3_SMEM_BYTES>>>();
    kh<<<1, 256>>>();
    kc<<<(NPIX + 255) / 256, 256>>>();
    ks<<<1, 1024>>>();
    kmask<<<KTOP, KTOP>>>();
    kseq<<<1, 512>>>((float*)d_out);
}

// round 10
// speedup vs baseline: 1.3045x; 1.0891x over previous
#include <cuda_runtime.h>
#include <math.h>
#include <stdint.h>

// ---------------- problem constants ----------------
#define H_IN 2048
#define W_IN 2048
#define P1   1023            // after conv1(2046) + maxpool2
#define C2   1021            // after conv2
#define H2S  1024            // padded row stride for h2
#define C3   1019            // after conv3
#define NPIX (C3*C3)         // 1038361
#define NBINS 8192
#define CANDMAX 4096
#define KTOP 512

typedef unsigned long long ull;

// ---------------- scratch (device globals) ----------
__device__ float g_pool1[10 * P1 * P1];
__device__ float g_h2p[16 * C2 * H2S];      // padded stride 1024
__device__ float g_prob[NPIX];
__device__ float4 g_reg[NPIX];
__device__ int   g_hist[NBINS];
__device__ int   g_cut;
__device__ int   g_cnt;
__device__ unsigned long long g_cand[CANDMAX];
__device__ float g_box5[KTOP * 5];
__device__ unsigned g_mask0[KTOP * 16];
__device__ unsigned g_mask1[KTOP * 16];
__device__ float g_stage[6632];
__device__ ull   g_stage2[462];
// duplicated {w,w} weights, padded to 10 per (c,o) group
__device__ float4 g_wd2[10 * 16 * 10 / 2];   // 800 float4
__device__ float4 g_wd3[16 * 32 * 10 / 2];   // 2560 float4

// ---------------- packed constant scalars -------
#define OW1 0
#define OB1 270
#define OP1 280
#define OW2 290
#define OB2 1730
#define OP2 1746
#define OW3 1762
#define OB3 6370
#define OP3 6402
#define OWA 6434
#define OBA 6498
#define OWB 6500
#define OBB 6628
#define NCONST 6632
__constant__ float cAll[NCONST];
__constant__ ull cDup[462];   // k1 weights (270), head wa (64), head wb (128)

#define CB1(i) cAll[OB1 + (i)]
#define CP1(i) cAll[OP1 + (i)]
#define CB2(i) cAll[OB2 + (i)]
#define CP2(i) cAll[OP2 + (i)]
#define CB3(i) cAll[OB3 + (i)]
#define CP3(i) cAll[OP3 + (i)]
#define CBA(i) cAll[OBA + (i)]
#define CBB(i) cAll[OBB + (i)]
#define D1(i)  cDup[(i)]
#define DWA(i) cDup[270 + (i)]
#define DWB(i) cDup[334 + (i)]

// ---------------- f32x2 helpers ----------------
__device__ __forceinline__ ull pk2(float lo, float hi) {
    ull r; asm("mov.b64 %0, {%1, %2};" : "=l"(r) : "f"(lo), "f"(hi)); return r;
}
__device__ __forceinline__ void up2(float& lo, float& hi, ull v) {
    asm("mov.b64 {%0, %1}, %2;" : "=f"(lo), "=f"(hi) : "l"(v));
}
__device__ __forceinline__ void ffma2(ull& d, ull a, ull b) {
    asm("fma.rn.f32x2 %0, %1, %2, %0;" : "+l"(d) : "l"(a), "l"(b));
}

// ============ KP: pack weights ============
__global__ void kpack(const float* w1, const float* b1, const float* p1,
                      const float* w2, const float* b2, const float* p2,
                      const float* w3, const float* b3, const float* p3,
                      const float* wa, const float* ba,
                      const float* wb, const float* bb) {
    int t = threadIdx.x;
    for (int i = t; i < 270; i += 256) g_stage[OW1 + i] = w1[i];
    if (t < 10) g_stage[OB1 + t] = b1[t];
    if (t < 10) g_stage[OP1 + t] = p1[t];
    for (int i = t; i < 1440; i += 256) g_stage[OW2 + i] = w2[i];
    if (t < 16) g_stage[OB2 + t] = b2[t];
    if (t < 16) g_stage[OP2 + t] = p2[t];
    for (int i = t; i < 4608; i += 256) g_stage[OW3 + i] = w3[i];
    if (t < 32) g_stage[OB3 + t] = b3[t];
    if (t < 32) g_stage[OP3 + t] = p3[t];
    if (t < 64) g_stage[OWA + t] = wa[t];
    if (t < 2)  g_stage[OBA + t] = ba[t];
    for (int i = t; i < 128; i += 256) g_stage[OWB + i] = wb[i];
    if (t < 4)  g_stage[OBB + t] = bb[t];

    for (int i = t; i < 270; i += 256) {
        unsigned u = __float_as_uint(w1[i]);
        g_stage2[i] = ((ull)u << 32) | u;
    }
    if (t < 64) {
        unsigned u = __float_as_uint(wa[t]);
        g_stage2[270 + t] = ((ull)u << 32) | u;
    }
    for (int i = t; i < 128; i += 256) {
        unsigned u = __float_as_uint(wb[i]);
        g_stage2[334 + i] = ((ull)u << 32) | u;
    }

    // k2: wd2[(c*16+o)*10 + k] = {w,w}
    float* d2 = (float*)g_wd2;
    for (int idx = t; idx < 1440; idx += 256) {
        int k = idx % 9, rest = idx / 9;
        int o = rest % 16, c = rest / 16;
        float w = w2[o * 90 + c * 9 + k];
        int g = (c * 16 + o) * 10 + k;
        d2[g * 2] = w; d2[g * 2 + 1] = w;
    }
    for (int g = t; g < 160; g += 256) {
        d2[(g * 10 + 9) * 2] = 0.f; d2[(g * 10 + 9) * 2 + 1] = 0.f;
    }
    // k3: wd3[(c*32+o)*10 + k] = {w,w}
    float* d3 = (float*)g_wd3;
    for (int idx = t; idx < 4608; idx += 256) {
        int k = idx % 9, rest = idx / 9;
        int o = rest % 32, c = rest / 32;
        float w = w3[o * 144 + c * 9 + k];
        int g = (c * 32 + o) * 10 + k;
        d3[g * 2] = w; d3[g * 2 + 1] = w;
    }
    for (int g = t; g < 512; g += 256) {
        d3[(g * 10 + 9) * 2] = 0.f; d3[(g * 10 + 9) * 2 + 1] = 0.f;
    }
}

// ============ K1: conv1(3->10,3x3) + PReLU + maxpool2, f32x2 ============
__global__ __launch_bounds__(256) void k1(const float* __restrict__ x) {
    int j = blockIdx.x * 16 + threadIdx.x;
    int i = blockIdx.y * 16 + threadIdx.y;
    if (i >= P1 || j >= P1) return;

    ull a01[10], a23[10];
#pragma unroll
    for (int co = 0; co < 10; co++) {
        float b = CB1(co);
        a01[co] = pk2(b, b);
        a23[co] = pk2(b, b);
    }

#pragma unroll
    for (int c = 0; c < 3; c++) {
        const float* xp = x + c * H_IN * W_IN + (2 * i) * W_IN + 2 * j;
        ull t2[4][3];
#pragma unroll
        for (int a = 0; a < 4; a++) {
            const float2* rp = reinterpret_cast<const float2*>(xp + a * W_IN);
            float2 u = rp[0], v = rp[1];
            t2[a][0] = pk2(u.x, u.y);
            t2[a][1] = pk2(u.y, v.x);
            t2[a][2] = pk2(v.x, v.y);
        }
#pragma unroll
        for (int co = 0; co < 10; co++)
#pragma unroll
            for (int dy = 0; dy < 3; dy++)
#pragma unroll
                for (int dx = 0; dx < 3; dx++) {
                    ull w = D1(((co * 3 + c) * 3 + dy) * 3 + dx);
                    ffma2(a01[co], t2[dy][dx], w);
                    ffma2(a23[co], t2[dy + 1][dx], w);
                }
    }

#pragma unroll
    for (int co = 0; co < 10; co++) {
        float a00, a01v, a10, a11;
        up2(a00, a01v, a01[co]);
        up2(a10, a11, a23[co]);
        float al = CP1(co);
        a00  = (a00  >= 0.f) ? a00  : al * a00;
        a01v = (a01v >= 0.f) ? a01v : al * a01v;
        a10  = (a10  >= 0.f) ? a10  : al * a10;
        a11  = (a11  >= 0.f) ? a11  : al * a11;
        g_pool1[co * P1 * P1 + i * P1 + j] = fmaxf(fmaxf(a00, a01v), fmaxf(a10, a11));
    }
}

// ============ K2: conv2(10->16) + PReLU, 4 px/thread, 128-thr blocks ======
#define K2_TW 36
#define K2_DATA (10 * 18 * K2_TW)
#define K2_SMEM_BYTES (K2_DATA * 4 + 10 * 16 * 10 * 8)

__global__ __launch_bounds__(128, 4) void k2() {
    extern __shared__ float dy2[];
    float (*s)[18][K2_TW] = (float(*)[18][K2_TW])dy2;
    ull* wsm = (ull*)(dy2 + K2_DATA);

    int tx = threadIdx.x, ty = threadIdx.y;       // 8 x 16
    int tid = ty * 8 + tx;
    int ox0 = blockIdx.x * 32, oy0 = blockIdx.y * 16;

    {
        float4* wv = (float4*)wsm;
        for (int i = tid; i < 800; i += 128) wv[i] = g_wd2[i];
    }
    for (int idx = tid; idx < 10 * 18 * 34; idx += 128) {
        int c = idx / (18 * 34);
        int rem = idx - c * (18 * 34);
        int r = rem / 34;
        int cc = rem - r * 34;
        int gy = oy0 + r, gx = ox0 + cc;
        s[c][r][cc] = (gy < P1 && gx < P1) ? g_pool1[c * P1 * P1 + gy * P1 + gx] : 0.f;
    }
    __syncthreads();

    int ox = ox0 + tx * 4, oy = oy0 + ty;

    ull accA[16], accB[16];
#pragma unroll
    for (int o = 0; o < 16; o++) {
        float b = CB2(o);
        accA[o] = pk2(b, b);
        accB[o] = pk2(b, b);
    }

#pragma unroll 1
    for (int c = 0; c < 10; c++) {
        ull q[3][5];
#pragma unroll
        for (int r = 0; r < 3; r++) {
            const float* row = &s[c][ty + r][tx * 4];
            float4 A = *reinterpret_cast<const float4*>(row);
            float2 B = *reinterpret_cast<const float2*>(row + 4);
            q[r][0] = pk2(A.x, A.y);
            q[r][1] = pk2(A.y, A.z);
            q[r][2] = pk2(A.z, A.w);
            q[r][3] = pk2(A.w, B.x);
            q[r][4] = pk2(B.x, B.y);
        }
        const ull* wc = wsm + c * 160;
#pragma unroll
        for (int o = 0; o < 16; o++) {
            const ull* w = wc + o * 10;
            ulonglong2 p0 = *(const ulonglong2*)(w + 0);
            ulonglong2 p1 = *(const ulonglong2*)(w + 2);
            ulonglong2 p2 = *(const ulonglong2*)(w + 4);
            ulonglong2 p3 = *(const ulonglong2*)(w + 6);
            ull p8 = w[8];
            ffma2(accA[o], q[0][0], p0.x); ffma2(accB[o], q[0][2], p0.x);
            ffma2(accA[o], q[0][1], p0.y); ffma2(accB[o], q[0][3], p0.y);
            ffma2(accA[o], q[0][2], p1.x); ffma2(accB[o], q[0][4], p1.x);
            ffma2(accA[o], q[1][0], p1.y); ffma2(accB[o], q[1][2], p1.y);
            ffma2(accA[o], q[1][1], p2.x); ffma2(accB[o], q[1][3], p2.x);
            ffma2(accA[o], q[1][2], p2.y); ffma2(accB[o], q[1][4], p2.y);
            ffma2(accA[o], q[2][0], p3.x); ffma2(accB[o], q[2][2], p3.x);
            ffma2(accA[o], q[2][1], p3.y); ffma2(accB[o], q[2][3], p3.y);
            ffma2(accA[o], q[2][2], p8);   ffma2(accB[o], q[2][4], p8);
        }
    }

    if (oy < C2) {
        int base = oy * H2S + ox;
#pragma unroll
        for (int o = 0; o < 16; o++) {
            float v0, v1, v2, v3;
            up2(v0, v1, accA[o]);
            up2(v2, v3, accB[o]);
            float al = CP2(o);
            v0 = (v0 >= 0.f) ? v0 : al * v0;
            v1 = (v1 >= 0.f) ? v1 : al * v1;
            v2 = (v2 >= 0.f) ? v2 : al * v2;
            v3 = (v3 >= 0.f) ? v3 : al * v3;
            float* op = g_h2p + o * (C2 * H2S) + base;
            if (ox + 3 < C2) {
                *reinterpret_cast<float4*>(op) = make_float4(v0, v1, v2, v3);
            } else {
                if (ox < C2)     op[0] = v0;
                if (ox + 1 < C2) op[1] = v1;
                if (ox + 2 < C2) op[2] = v2;
                if (ox + 3 < C2) op[3] = v3;
            }
        }
    }
}

// ============ K3: conv3(16->32) + PReLU + heads + softmax + hist ==========
// 4 px/thread, 8-output quarters, tile staged ONCE, weights per quarter.
#define K3_TW 36
#define K3_DATA (16 * 18 * K3_TW)            // 10368 floats = 41472 B
#define K3_WQ 1280                           // ull per quarter: 16c x 8oo x 10
#define K3_SMEM_BYTES (K3_DATA * 4 + K3_WQ * 8)   // 41472 + 10240 = 51712

__global__ __launch_bounds__(128, 4) void k3() {
    extern __shared__ float dy3[];
    float (*s)[18][K3_TW] = (float(*)[18][K3_TW])dy3;
    ull* wsm = (ull*)(dy3 + K3_DATA);

    int tx = threadIdx.x, ty = threadIdx.y;       // 8 x 16
    int tid = ty * 8 + tx;
    int ox0 = blockIdx.x * 32, oy0 = blockIdx.y * 16;
    int ox = ox0 + tx * 4, oy = oy0 + ty;

    // stage tile once
    for (int idx = tid; idx < 16 * 18 * 34; idx += 128) {
        int c = idx / (18 * 34);
        int rem = idx - c * (18 * 34);
        int r = rem / 34;
        int cc = rem - r * 34;
        int gy = oy0 + r, gx = ox0 + cc;
        s[c][r][cc] = (gy < C2 && gx < C2) ? g_h2p[c * (C2 * H2S) + gy * H2S + gx] : 0.f;
    }

    // head accumulators: c0,c1,r0..r3, each {pair01, pair23}
    ull hacc[12];
    {
        float b0 = CBA(0), b1 = CBA(1);
        hacc[0] = pk2(b0, b0); hacc[1] = pk2(b0, b0);
        hacc[2] = pk2(b1, b1); hacc[3] = pk2(b1, b1);
#pragma unroll
        for (int qq = 0; qq < 4; qq++) {
            float b = CBB(qq);
            hacc[4 + qq * 2] = pk2(b, b);
            hacc[5 + qq * 2] = pk2(b, b);
        }
    }

#pragma unroll 1
    for (int og = 0; og < 4; og++) {
        __syncthreads();   // og=0: also covers tile staging
        {
            float4* wv = (float4*)wsm;
            for (int i = tid; i < 640; i += 128) {
                int grp = i / 5, k4 = i - grp * 5;
                int c = grp >> 3, oo = grp & 7;
                wv[i] = g_wd3[(c * 32 + og * 8 + oo) * 5 + k4];
            }
        }
        __syncthreads();

        ull accA[8], accB[8];
#pragma unroll
        for (int oo = 0; oo < 8; oo++) {
            float b = CB3(og * 8 + oo);
            ull bb = pk2(b, b);
            accA[oo] = bb; accB[oo] = bb;
        }

#pragma unroll 1
        for (int c = 0; c < 16; c++) {
            ull q[3][5];
#pragma unroll
            for (int r = 0; r < 3; r++) {
                const float* row = &s[c][ty + r][tx * 4];
                float4 A = *reinterpret_cast<const float4*>(row);
                float2 B = *reinterpret_cast<const float2*>(row + 4);
                q[r][0] = pk2(A.x, A.y);
                q[r][1] = pk2(A.y, A.z);
                q[r][2] = pk2(A.z, A.w);
                q[r][3] = pk2(A.w, B.x);
                q[r][4] = pk2(B.x, B.y);
            }
            const ull* wc = wsm + c * 80;
#pragma unroll
            for (int oo = 0; oo < 8; oo++) {
                const ull* w = wc + oo * 10;
                ulonglong2 p0 = *(const ulonglong2*)(w + 0);
                ulonglong2 p1 = *(const ulonglong2*)(w + 2);
                ulonglong2 p2 = *(const ulonglong2*)(w + 4);
                ulonglong2 p3 = *(const ulonglong2*)(w + 6);
                ull p8 = w[8];
                ffma2(accA[oo], q[0][0], p0.x); ffma2(accB[oo], q[0][2], p0.x);
                ffma2(accA[oo], q[0][1], p0.y); ffma2(accB[oo], q[0][3], p0.y);
                ffma2(accA[oo], q[0][2], p1.x); ffma2(accB[oo], q[0][4], p1.x);
                ffma2(accA[oo], q[1][0], p1.y); ffma2(accB[oo], q[1][2], p1.y);
                ffma2(accA[oo], q[1][1], p2.x); ffma2(accB[oo], q[1][3], p2.x);
                ffma2(accA[oo], q[1][2], p2.y); ffma2(accB[oo], q[1][4], p2.y);
                ffma2(accA[oo], q[2][0], p3.x); ffma2(accB[oo], q[2][2], p3.x);
                ffma2(accA[oo], q[2][1], p3.y); ffma2(accB[oo], q[2][3], p3.y);
                ffma2(accA[oo], q[2][2], p8);   ffma2(accB[oo], q[2][4], p8);
            }
        }

        // PReLU + incremental head accumulation for this quarter
#pragma unroll
        for (int oo = 0; oo < 8; oo++) {
            int o = og * 8 + oo;
            float al = CP3(o);
            float v0, v1, v2, v3;
            up2(v0, v1, accA[oo]);
            up2(v2, v3, accB[oo]);
            v0 = (v0 >= 0.f) ? v0 : al * v0;
            v1 = (v1 >= 0.f) ? v1 : al * v1;
            v2 = (v2 >= 0.f) ? v2 : al * v2;
            v3 = (v3 >= 0.f) ? v3 : al * v3;
            ull p01 = pk2(v0, v1), p23 = pk2(v2, v3);
            ull wa0 = DWA(o), wa1 = DWA(32 + o);
            ffma2(hacc[0], p01, wa0); ffma2(hacc[1], p23, wa0);
            ffma2(hacc[2], p01, wa1); ffma2(hacc[3], p23, wa1);
#pragma unroll
            for (int qq = 0; qq < 4; qq++) {
                ull wq = DWB(qq * 32 + o);
                ffma2(hacc[4 + qq * 2], p01, wq);
                ffma2(hacc[5 + qq * 2], p23, wq);
            }
        }
    }

    if (oy >= C3) return;

    float c0v[4], c1v[4], rv[4][4];
    up2(c0v[0], c0v[1], hacc[0]); up2(c0v[2], c0v[3], hacc[1]);
    up2(c1v[0], c1v[1], hacc[2]); up2(c1v[2], c1v[3], hacc[3]);
#pragma unroll
    for (int qq = 0; qq < 4; qq++) {
        up2(rv[qq][0], rv[qq][1], hacc[4 + qq * 2]);
        up2(rv[qq][2], rv[qq][3], hacc[5 + qq * 2]);
    }

#pragma unroll
    for (int px = 0; px < 4; px++) {
        int oxx = ox + px;
        if (oxx >= C3) break;
        float c0 = c0v[px], c1 = c1v[px];
        float mx = fmaxf(c0, c1);
        float e0 = expf(c0 - mx), e1 = expf(c1 - mx);
        float pr = e1 / (e0 + e1);

        int pix = oy * C3 + oxx;
        g_prob[pix] = pr;
        g_reg[pix] = make_float4(rv[0][px], rv[1][px], rv[2][px], rv[3][px]);

        if (pr >= 0.6f) {
            int bin = (int)((pr - 0.6f) * 20480.f);
            if (bin > NBINS - 1) bin = NBINS - 1;
            atomicAdd(&g_hist[bin], 1);
        }
    }
}

// ============ KH: find histogram cutoff bin ============
__global__ void kh() {
    __shared__ int csum[256];
    int t = threadIdx.x;
    int sum = 0;
    for (int b = t * 32; b < t * 32 + 32; b++) sum += g_hist[b];
    csum[t] = sum;
    __syncthreads();
    int chunk = sum;
    for (int off = 1; off < 256; off <<= 1) {
        int v = csum[t] + ((t + off < 256) ? csum[t + off] : 0);
        __syncthreads();
        csum[t] = v;
        __syncthreads();
    }
    int total = csum[0];
    if (t == 0 && total < KTOP) g_cut = 0;
    int suf_excl = (t < 255) ? csum[t + 1] : 0;
    if (suf_excl < KTOP && suf_excl + chunk >= KTOP) {
        int s = suf_excl;
        int B = t * 32;
        for (int b = t * 32 + 31; b >= t * 32; b--) {
            s += g_hist[b];
            if (s >= KTOP) { B = b; break; }
        }
        g_cut = B;
    }
}

// ============ KC: compact candidates >= cutoff bin ============
__global__ void kc() {
    int i = blockIdx.x * 256 + threadIdx.x;
    if (i >= NPIX) return;
    float pr = g_prob[i];
    if (pr < 0.6f) return;
    int bin = (int)((pr - 0.6f) * 20480.f);
    if (bin > NBINS - 1) bin = NBINS - 1;
    if (bin < g_cut) return;
    int pos = atomicAdd(&g_cnt, 1);
    if (pos < CANDMAX) {
        unsigned long long key =
            ((unsigned long long)__float_as_uint(pr) << 32) |
            (unsigned long long)(~(unsigned)i);
        g_cand[pos] = key;
    }
}

// ============ KS: bitonic sort desc + decode boxes ============
__global__ void ks() {
    __shared__ unsigned long long a[CANDMAX];
    int tid = threadIdx.x;
    int cnt = g_cnt;
    if (cnt > CANDMAX) cnt = CANDMAX;
    for (int i = tid; i < CANDMAX; i += 1024) a[i] = (i < cnt) ? g_cand[i] : 0ULL;
    __syncthreads();

    for (int k = 2; k <= CANDMAX; k <<= 1) {
        for (int j = k >> 1; j > 0; j >>= 1) {
            for (int i = tid; i < CANDMAX; i += 1024) {
                int ixj = i ^ j;
                if (ixj > i) {
                    unsigned long long A = a[i], B = a[ixj];
                    bool desc = ((i & k) == 0);
                    if (desc ? (A < B) : (A > B)) { a[i] = B; a[ixj] = A; }
                }
            }
            __syncthreads();
        }
    }

    if (tid < KTOP) {
        unsigned long long key = a[tid];
        unsigned sb = (unsigned)(key >> 32);
        float sc = sb ? __uint_as_float(sb) : -1.0f;
        float x1 = 0.f, y1 = 0.f, x2 = 0.f, y2 = 0.f;
        if (sc >= 0.6f) {
            unsigned idx = ~(unsigned)(key & 0xFFFFFFFFu);
            float4 rg = g_reg[idx];
            float yy = (float)(idx / C3);
            float xx = (float)(idx % C3);
            float cx = (xx * 2.0f + 6.0f) / 0.6f;
            float cy = (yy * 2.0f + 6.0f) / 0.6f;
            const float ww = 12.0f / 0.6f;
            x1 = cx - ww * 0.5f + rg.x * ww;
            y1 = cy - ww * 0.5f + rg.y * ww;
            x2 = cx + ww * 0.5f + rg.z * ww;
            y2 = cy + ww * 0.5f + rg.w * ww;
        }
        g_box5[tid * 5 + 0] = x1;
        g_box5[tid * 5 + 1] = y1;
        g_box5[tid * 5 + 2] = x2;
        g_box5[tid * 5 + 3] = y2;
        g_box5[tid * 5 + 4] = sc;
    }
}

// ============ KM: build suppression bitmasks ============
__global__ void kmask() {
    int i = blockIdx.x;
    int t = threadIdx.x;
    float ax1 = g_box5[i * 5 + 0], ay1 = g_box5[i * 5 + 1];
    float ax2 = g_box5[i * 5 + 2], ay2 = g_box5[i * 5 + 3];
    float bx1 = g_box5[t * 5 + 0], by1 = g_box5[t * 5 + 1];
    float bx2 = g_box5[t * 5 + 2], by2 = g_box5[t * 5 + 3];
    float aar = (ax2 - ax1) * (ay2 - ay1);
    float bar = (bx2 - bx1) * (by2 - by1);
    float xi1 = fmaxf(ax1, bx1), yi1 = fmaxf(ay1, by1);
    float xi2 = fminf(ax2, bx2), yi2 = fminf(ay2, by2);
    float inter = fmaxf(xi2 - xi1, 0.f) * fmaxf(yi2 - yi1, 0.f);
    float iou = inter / (aar + bar - inter + 1e-9f);
    bool gt = (t > i);
    unsigned b0 = __ballot_sync(0xFFFFFFFFu, gt && (iou > 0.5f));
    unsigned b1 = __ballot_sync(0xFFFFFFFFu, gt && (iou > 0.7f));
    if ((t & 31) == 0) {
        g_mask0[i * 16 + (t >> 5)] = b0;
        g_mask1[i * 16 + (t >> 5)] = b1;
    }
}

// ============ KQ: sequential keep-propagation + output ============
__global__ void kseq(float* __restrict__ out) {
    __shared__ unsigned sm[KTOP * 16];
    __shared__ unsigned skw[16];
    int t = threadIdx.x;
    float x1 = g_box5[t * 5 + 0];
    float y1 = g_box5[t * 5 + 1];
    float x2 = g_box5[t * 5 + 2];
    float y2 = g_box5[t * 5 + 3];
    float sc = g_box5[t * 5 + 4];
    unsigned bal = __ballot_sync(0xFFFFFFFFu, sc >= 0.6f);
    if ((t & 31) == 0) skw[t >> 5] = bal;

    for (int pass = 0; pass < 2; pass++) {
        const unsigned* gm = pass ? g_mask1 : g_mask0;
        for (int i = t; i < KTOP * 16; i += 512) sm[i] = gm[i];
        __syncthreads();
        if (t < 32) {
            unsigned k = (t < 16) ? skw[t] : 0u;
            for (int w = 0; w < 16; w++) {
                unsigned done = 0;
                while (true) {
                    unsigned cur = __shfl_sync(0xFFFFFFFFu, k, w) & ~done;
                    if (!cur) break;
                    int b = __ffs(cur) - 1;
                    done |= (1u << b);
                    int i = w * 32 + b;
                    unsigned m = (t < 16) ? sm[i * 16 + t] : 0u;
                    k &= ~m;
                }
            }
            if (t < 16) skw[t] = k;
        }
        __syncthreads();
    }

    float m = ((skw[t >> 5] >> (t & 31)) & 1u) ? 1.f : 0.f;
    out[t * 5 + 0] = x1 * m;
    out[t * 5 + 1] = y1 * m;
    out[t * 5 + 2] = x2 * m;
    out[t * 5 + 3] = y2 * m;
    out[t * 5 + 4] = sc * m;
}

// ---------------- host launcher ----------------
extern "C" void kernel_launch(void* const* d_in, const int* in_sizes, int n_in,
                              void* d_out, int out_size) {
    const float* x = (const float*)d_in[0];

    kpack<<<1, 256>>>((const float*)d_in[1], (const float*)d_in[2], (const float*)d_in[3],
                      (const float*)d_in[4], (const float*)d_in[5], (const float*)d_in[6],
                      (const float*)d_in[7], (const float*)d_in[8], (const float*)d_in[9],
                      (const float*)d_in[10], (const float*)d_in[11],
                      (const float*)d_in[12], (const float*)d_in[13]);

    void* sp = 0; cudaGetSymbolAddress(&sp, g_stage);
    cudaMemcpyToSymbolAsync(cAll, sp, NCONST * sizeof(float), 0, cudaMemcpyDeviceToDevice);
    void* sp2 = 0; cudaGetSymbolAddress(&sp2, g_stage2);
    cudaMemcpyToSymbolAsync(cDup, sp2, 462 * sizeof(ull), 0, cudaMemcpyDeviceToDevice);

    void* hp = 0; cudaGetSymbolAddress(&hp, g_hist);
    cudaMemsetAsync(hp, 0, NBINS * sizeof(int));
    void* cp = 0; cudaGetSymbolAddress(&cp, g_cnt);
    cudaMemsetAsync(cp, 0, sizeof(int));

    cudaFuncSetAttribute(k2, cudaFuncAttributeMaxDynamicSharedMemorySize, K2_SMEM_BYTES);
    cudaFuncSetAttribute(k3, cudaFuncAttributeMaxDynamicSharedMemorySize, K3_SMEM_BYTES);

    k1<<<dim3(64, 64), dim3(16, 16)>>>(x);
    k2<<<dim3(32, 64), dim3(8, 16), K2_SMEM_BYTES>>>();
    k3<<<dim3(32, 64), dim3(8, 16), K3_SMEM_BYTES>>>();
    kh<<<1, 256>>>();
    kc<<<(NPIX + 255) / 256, 256>>>();
    ks<<<1, 1024>>>();
    kmask<<<KTOP, KTOP>>>();
    kseq<<<1, 512>>>((float*)d_out);
}

// round 12
// speedup vs baseline: 1.4495x; 1.1112x over previous
#include <cuda_runtime.h>
#include <math.h>
#include <stdint.h>

// ---------------- problem constants ----------------
#define H_IN 2048
#define W_IN 2048
#define P1   1023            // after conv1(2046) + maxpool2
#define C2   1021            // after conv2
#define H2S  1024            // padded row stride for h2
#define C3   1019            // after conv3
#define NPIX (C3*C3)         // 1038361
#define NBINS 8192
#define CANDMAX 4096
#define KTOP 512

typedef unsigned long long ull;

// ---------------- scratch (device globals) ----------
__device__ float g_pool1[10 * P1 * P1];
__device__ float g_h2p[16 * C2 * H2S];      // padded stride 1024
__device__ float g_prob[NPIX];
__device__ float4 g_reg[NPIX];
__device__ int   g_hist[NBINS];
__device__ int   g_cut;
__device__ int   g_cnt;
__device__ unsigned long long g_cand[CANDMAX];
__device__ float g_box5[KTOP * 5];
__device__ unsigned g_mask0[KTOP * 16];
__device__ unsigned g_mask1[KTOP * 16];
__device__ float g_stage[6632];
__device__ ull   g_stage2[462];
// duplicated {w,w} weights, padded to 10 per (c,o) group
__device__ float4 g_wd2[10 * 16 * 10 / 2];   // 800 float4
__device__ float4 g_wd3[16 * 32 * 10 / 2];   // 2560 float4

// ---------------- packed constant scalars -------
#define OW1 0
#define OB1 270
#define OP1 280
#define OW2 290
#define OB2 1730
#define OP2 1746
#define OW3 1762
#define OB3 6370
#define OP3 6402
#define OWA 6434
#define OBA 6498
#define OWB 6500
#define OBB 6628
#define NCONST 6632
__constant__ float cAll[NCONST];
__constant__ ull cDup[462];   // k1 weights (270), head wa (64), head wb (128)

#define CB1(i) cAll[OB1 + (i)]
#define CP1(i) cAll[OP1 + (i)]
#define CB2(i) cAll[OB2 + (i)]
#define CP2(i) cAll[OP2 + (i)]
#define CB3(i) cAll[OB3 + (i)]
#define CP3(i) cAll[OP3 + (i)]
#define CBA(i) cAll[OBA + (i)]
#define CBB(i) cAll[OBB + (i)]
#define D1(i)  cDup[(i)]
#define DWA(i) cDup[270 + (i)]
#define DWB(i) cDup[334 + (i)]

// ---------------- f32x2 helpers ----------------
__device__ __forceinline__ ull pk2(float lo, float hi) {
    ull r; asm("mov.b64 %0, {%1, %2};" : "=l"(r) : "f"(lo), "f"(hi)); return r;
}
__device__ __forceinline__ void up2(float& lo, float& hi, ull v) {
    asm("mov.b64 {%0, %1}, %2;" : "=f"(lo), "=f"(hi) : "l"(v));
}
__device__ __forceinline__ void ffma2(ull& d, ull a, ull b) {
    asm("fma.rn.f32x2 %0, %1, %2, %0;" : "+l"(d) : "l"(a), "l"(b));
}

// ============ KP: pack weights ============
__global__ void kpack(const float* w1, const float* b1, const float* p1,
                      const float* w2, const float* b2, const float* p2,
                      const float* w3, const float* b3, const float* p3,
                      const float* wa, const float* ba,
                      const float* wb, const float* bb) {
    int t = threadIdx.x;
    for (int i = t; i < 270; i += 256) g_stage[OW1 + i] = w1[i];
    if (t < 10) g_stage[OB1 + t] = b1[t];
    if (t < 10) g_stage[OP1 + t] = p1[t];
    for (int i = t; i < 1440; i += 256) g_stage[OW2 + i] = w2[i];
    if (t < 16) g_stage[OB2 + t] = b2[t];
    if (t < 16) g_stage[OP2 + t] = p2[t];
    for (int i = t; i < 4608; i += 256) g_stage[OW3 + i] = w3[i];
    if (t < 32) g_stage[OB3 + t] = b3[t];
    if (t < 32) g_stage[OP3 + t] = p3[t];
    if (t < 64) g_stage[OWA + t] = wa[t];
    if (t < 2)  g_stage[OBA + t] = ba[t];
    for (int i = t; i < 128; i += 256) g_stage[OWB + i] = wb[i];
    if (t < 4)  g_stage[OBB + t] = bb[t];

    for (int i = t; i < 270; i += 256) {
        unsigned u = __float_as_uint(w1[i]);
        g_stage2[i] = ((ull)u << 32) | u;
    }
    if (t < 64) {
        unsigned u = __float_as_uint(wa[t]);
        g_stage2[270 + t] = ((ull)u << 32) | u;
    }
    for (int i = t; i < 128; i += 256) {
        unsigned u = __float_as_uint(wb[i]);
        g_stage2[334 + i] = ((ull)u << 32) | u;
    }

    // k2: wd2[(c*16+o)*10 + k] = {w,w}
    float* d2 = (float*)g_wd2;
    for (int idx = t; idx < 1440; idx += 256) {
        int k = idx % 9, rest = idx / 9;
        int o = rest % 16, c = rest / 16;
        float w = w2[o * 90 + c * 9 + k];
        int g = (c * 16 + o) * 10 + k;
        d2[g * 2] = w; d2[g * 2 + 1] = w;
    }
    for (int g = t; g < 160; g += 256) {
        d2[(g * 10 + 9) * 2] = 0.f; d2[(g * 10 + 9) * 2 + 1] = 0.f;
    }
    // k3: wd3[(c*32+o)*10 + k] = {w,w}
    float* d3 = (float*)g_wd3;
    for (int idx = t; idx < 4608; idx += 256) {
        int k = idx % 9, rest = idx / 9;
        int o = rest % 32, c = rest / 32;
        float w = w3[o * 144 + c * 9 + k];
        int g = (c * 32 + o) * 10 + k;
        d3[g * 2] = w; d3[g * 2 + 1] = w;
    }
    for (int g = t; g < 512; g += 256) {
        d3[(g * 10 + 9) * 2] = 0.f; d3[(g * 10 + 9) * 2 + 1] = 0.f;
    }
}

// ============ K1: conv1(3->10,3x3) + PReLU + maxpool2, f32x2 ============
__global__ __launch_bounds__(256) void k1(const float* __restrict__ x) {
    int j = blockIdx.x * 16 + threadIdx.x;
    int i = blockIdx.y * 16 + threadIdx.y;
    if (i >= P1 || j >= P1) return;

    ull a01[10], a23[10];
#pragma unroll
    for (int co = 0; co < 10; co++) {
        float b = CB1(co);
        a01[co] = pk2(b, b);
        a23[co] = pk2(b, b);
    }

#pragma unroll
    for (int c = 0; c < 3; c++) {
        const float* xp = x + c * H_IN * W_IN + (2 * i) * W_IN + 2 * j;
        ull t2[4][3];
#pragma unroll
        for (int a = 0; a < 4; a++) {
            const float2* rp = reinterpret_cast<const float2*>(xp + a * W_IN);
            float2 u = rp[0], v = rp[1];
            t2[a][0] = pk2(u.x, u.y);
            t2[a][1] = pk2(u.y, v.x);
            t2[a][2] = pk2(v.x, v.y);
        }
#pragma unroll
        for (int co = 0; co < 10; co++)
#pragma unroll
            for (int dy = 0; dy < 3; dy++)
#pragma unroll
                for (int dx = 0; dx < 3; dx++) {
                    ull w = D1(((co * 3 + c) * 3 + dy) * 3 + dx);
                    ffma2(a01[co], t2[dy][dx], w);
                    ffma2(a23[co], t2[dy + 1][dx], w);
                }
    }

#pragma unroll
    for (int co = 0; co < 10; co++) {
        float a00, a01v, a10, a11;
        up2(a00, a01v, a01[co]);
        up2(a10, a11, a23[co]);
        float al = CP1(co);
        a00  = (a00  >= 0.f) ? a00  : al * a00;
        a01v = (a01v >= 0.f) ? a01v : al * a01v;
        a10  = (a10  >= 0.f) ? a10  : al * a10;
        a11  = (a11  >= 0.f) ? a11  : al * a11;
        g_pool1[co * P1 * P1 + i * P1 + j] = fmaxf(fmaxf(a00, a01v), fmaxf(a10, a11));
    }
}

// ============ K2: conv2(10->16) + PReLU, row-pair f32x2, 2 cols/thread ====
// lanes of f32x2 = rows (y, y+8); tile stored as float2{row r, row r+8}
#define K2_DATA2 (10 * 10 * 34)                    // float2 count = 3400
#define K2_SMEM_BYTES (K2_DATA2 * 8 + 10 * 16 * 10 * 8)   // 27200 + 12800 = 40000

__global__ __launch_bounds__(128, 4) void k2() {
    extern __shared__ float dy2[];
    float2* S = (float2*)dy2;
    ull* wsm = (ull*)(dy2 + K2_DATA2 * 2);

    int tx = threadIdx.x, ty = threadIdx.y;       // (16, 8)
    int tid = ty * 16 + tx;
    int ox0 = blockIdx.x * 32, oy0 = blockIdx.y * 16;
    int ox = ox0 + 2 * tx, oy = oy0 + ty;

    {
        float4* wv = (float4*)wsm;
        for (int i = tid; i < 800; i += 128) wv[i] = g_wd2[i];
    }
    // stage tile: S[(c*10+r)*34 + x] = {in[oy0+r][x], in[oy0+r+8][x]}
    for (int i = tid; i < 10 * 10 * 34; i += 128) {
        int c = i / 340; int rem = i - c * 340;
        int r = rem / 34; int xx = rem - r * 34;
        int gx = ox0 + xx;
        int gyl = oy0 + r, gyh = gyl + 8;
        const float* pl = g_pool1 + c * P1 * P1;
        float lo = (gyl < P1 && gx < P1) ? pl[gyl * P1 + gx] : 0.f;
        float hi = (gyh < P1 && gx < P1) ? pl[gyh * P1 + gx] : 0.f;
        S[(c * 10 + r) * 34 + xx] = make_float2(lo, hi);
    }
    __syncthreads();

    ull accA[16], accB[16];   // accA = col ox (rows y,y+8), accB = col ox+1
#pragma unroll
    for (int o = 0; o < 16; o++) {
        float b = CB2(o);
        accA[o] = pk2(b, b);
        accB[o] = pk2(b, b);
    }

#pragma unroll 1
    for (int c = 0; c < 10; c++) {
        ull t[3][4];
#pragma unroll
        for (int dy = 0; dy < 3; dy++) {
            const ull* rp = (const ull*)&S[(c * 10 + ty + dy) * 34 + 2 * tx];
            ulonglong2 u0 = *(const ulonglong2*)rp;
            ulonglong2 u1 = *(const ulonglong2*)(rp + 2);
            t[dy][0] = u0.x; t[dy][1] = u0.y; t[dy][2] = u1.x; t[dy][3] = u1.y;
        }
        const ull* wc = wsm + c * 160;
#pragma unroll
        for (int o = 0; o < 16; o++) {
            const ull* w = wc + o * 10;
            ulonglong2 p0 = *(const ulonglong2*)(w + 0);
            ulonglong2 p1 = *(const ulonglong2*)(w + 2);
            ulonglong2 p2 = *(const ulonglong2*)(w + 4);
            ulonglong2 p3 = *(const ulonglong2*)(w + 6);
            ull p8 = w[8];
            ffma2(accA[o], t[0][0], p0.x); ffma2(accB[o], t[0][1], p0.x);
            ffma2(accA[o], t[0][1], p0.y); ffma2(accB[o], t[0][2], p0.y);
            ffma2(accA[o], t[0][2], p1.x); ffma2(accB[o], t[0][3], p1.x);
            ffma2(accA[o], t[1][0], p1.y); ffma2(accB[o], t[1][1], p1.y);
            ffma2(accA[o], t[1][1], p2.x); ffma2(accB[o], t[1][2], p2.x);
            ffma2(accA[o], t[1][2], p2.y); ffma2(accB[o], t[1][3], p2.y);
            ffma2(accA[o], t[2][0], p3.x); ffma2(accB[o], t[2][1], p3.x);
            ffma2(accA[o], t[2][1], p3.y); ffma2(accB[o], t[2][2], p3.y);
            ffma2(accA[o], t[2][2], p8);   ffma2(accB[o], t[2][3], p8);
        }
    }

#pragma unroll
    for (int o = 0; o < 16; o++) {
        float al = CP2(o);
        float aL, aH, bL, bH;
        up2(aL, aH, accA[o]);
        up2(bL, bH, accB[o]);
        aL = (aL >= 0.f) ? aL : al * aL;
        aH = (aH >= 0.f) ? aH : al * aH;
        bL = (bL >= 0.f) ? bL : al * bL;
        bH = (bH >= 0.f) ? bH : al * bH;
        float* pl = g_h2p + o * (C2 * H2S);
        if (oy < C2) {
            if (ox + 1 < C2) *reinterpret_cast<float2*>(pl + oy * H2S + ox) = make_float2(aL, bL);
            else if (ox < C2) pl[oy * H2S + ox] = aL;
        }
        int oy2 = oy + 8;
        if (oy2 < C2) {
            if (ox + 1 < C2) *reinterpret_cast<float2*>(pl + oy2 * H2S + ox) = make_float2(aH, bH);
            else if (ox < C2) pl[oy2 * H2S + ox] = aH;
        }
    }
}

// ============ K3: conv3(16->32) + PReLU + heads + softmax + hist ==========
// row-pair f32x2, 2 cols/thread, 8-output quarters, tile staged once
#define K3_DATA2 (16 * 10 * 34)                    // float2 count = 5440
#define K3_WQ 1280                                 // ull per quarter
#define K3_SMEM_BYTES (K3_DATA2 * 8 + K3_WQ * 8)   // 43520 + 10240 = 53760

__global__ __launch_bounds__(128, 4) void k3() {
    extern __shared__ float dy3[];
    float2* S = (float2*)dy3;
    ull* wsm = (ull*)(dy3 + K3_DATA2 * 2);

    int tx = threadIdx.x, ty = threadIdx.y;       // (16, 8)
    int tid = ty * 16 + tx;
    int ox0 = blockIdx.x * 32, oy0 = blockIdx.y * 16;
    int ox = ox0 + 2 * tx, oy = oy0 + ty;

    // stage tile once: S[(c*10+r)*34 + x] = {h2[oy0+r][x], h2[oy0+r+8][x]}
    for (int i = tid; i < 16 * 10 * 17; i += 128) {
        int c = i / 170; int rem = i - c * 170;
        int r = rem / 17; int j = rem - r * 17;
        int gx = ox0 + 2 * j;
        int gyl = oy0 + r, gyh = gyl + 8;
        const float* pl = g_h2p + c * (C2 * H2S);
        float2 a = make_float2(0.f, 0.f), b = make_float2(0.f, 0.f);
        if (gyl < C2) {
            if (gx + 1 < C2) a = *reinterpret_cast<const float2*>(pl + gyl * H2S + gx);
            else if (gx < C2) a.x = pl[gyl * H2S + gx];
        }
        if (gyh < C2) {
            if (gx + 1 < C2) b = *reinterpret_cast<const float2*>(pl + gyh * H2S + gx);
            else if (gx < C2) b.x = pl[gyh * H2S + gx];
        }
        float2* dst = S + (c * 10 + r) * 34 + 2 * j;
        dst[0] = make_float2(a.x, b.x);
        dst[1] = make_float2(a.y, b.y);
    }

    // head accumulators: c0,c1,r0..r3 x {colA, colB}; lanes = rows (y, y+8)
    ull hacc[12];
    {
        float b0 = CBA(0), b1 = CBA(1);
        hacc[0] = pk2(b0, b0); hacc[1] = pk2(b0, b0);
        hacc[2] = pk2(b1, b1); hacc[3] = pk2(b1, b1);
#pragma unroll
        for (int qq = 0; qq < 4; qq++) {
            float b = CBB(qq);
            hacc[4 + qq * 2] = pk2(b, b);
            hacc[5 + qq * 2] = pk2(b, b);
        }
    }

#pragma unroll 1
    for (int og = 0; og < 4; og++) {
        __syncthreads();   // og=0: also covers tile staging
        {
            float4* wv = (float4*)wsm;
            for (int i = tid; i < 640; i += 128) {
                int grp = i / 5, k4 = i - grp * 5;
                int c = grp >> 3, oo = grp & 7;
                wv[i] = g_wd3[(c * 32 + og * 8 + oo) * 5 + k4];
            }
        }
        __syncthreads();

        ull accA[8], accB[8];
#pragma unroll
        for (int oo = 0; oo < 8; oo++) {
            float b = CB3(og * 8 + oo);
            ull bb = pk2(b, b);
            accA[oo] = bb; accB[oo] = bb;
        }

#pragma unroll 1
        for (int c = 0; c < 16; c++) {
            ull t[3][4];
#pragma unroll
            for (int dy = 0; dy < 3; dy++) {
                const ull* rp = (const ull*)&S[(c * 10 + ty + dy) * 34 + 2 * tx];
                ulonglong2 u0 = *(const ulonglong2*)rp;
                ulonglong2 u1 = *(const ulonglong2*)(rp + 2);
                t[dy][0] = u0.x; t[dy][1] = u0.y; t[dy][2] = u1.x; t[dy][3] = u1.y;
            }
            const ull* wc = wsm + c * 80;
#pragma unroll
            for (int oo = 0; oo < 8; oo++) {
                const ull* w = wc + oo * 10;
                ulonglong2 p0 = *(const ulonglong2*)(w + 0);
                ulonglong2 p1 = *(const ulonglong2*)(w + 2);
                ulonglong2 p2 = *(const ulonglong2*)(w + 4);
                ulonglong2 p3 = *(const ulonglong2*)(w + 6);
                ull p8 = w[8];
                ffma2(accA[oo], t[0][0], p0.x); ffma2(accB[oo], t[0][1], p0.x);
                ffma2(accA[oo], t[0][1], p0.y); ffma2(accB[oo], t[0][2], p0.y);
                ffma2(accA[oo], t[0][2], p1.x); ffma2(accB[oo], t[0][3], p1.x);
                ffma2(accA[oo], t[1][0], p1.y); ffma2(accB[oo], t[1][1], p1.y);
                ffma2(accA[oo], t[1][1], p2.x); ffma2(accB[oo], t[1][2], p2.x);
                ffma2(accA[oo], t[1][2], p2.y); ffma2(accB[oo], t[1][3], p2.y);
                ffma2(accA[oo], t[2][0], p3.x); ffma2(accB[oo], t[2][1], p3.x);
                ffma2(accA[oo], t[2][1], p3.y); ffma2(accB[oo], t[2][2], p3.y);
                ffma2(accA[oo], t[2][2], p8);   ffma2(accB[oo], t[2][3], p8);
            }
        }

        // PReLU + incremental head accumulation for this quarter
#pragma unroll
        for (int oo = 0; oo < 8; oo++) {
            int o = og * 8 + oo;
            float al = CP3(o);
            float aL, aH, bL, bH;
            up2(aL, aH, accA[oo]);
            up2(bL, bH, accB[oo]);
            aL = (aL >= 0.f) ? aL : al * aL;
            aH = (aH >= 0.f) ? aH : al * aH;
            bL = (bL >= 0.f) ? bL : al * bL;
            bH = (bH >= 0.f) ? bH : al * bH;
            ull pA = pk2(aL, aH), pB = pk2(bL, bH);
            ull wa0 = DWA(o), wa1 = DWA(32 + o);
            ffma2(hacc[0], pA, wa0); ffma2(hacc[1], pB, wa0);
            ffma2(hacc[2], pA, wa1); ffma2(hacc[3], pB, wa1);
#pragma unroll
            for (int qq = 0; qq < 4; qq++) {
                ull wq = DWB(qq * 32 + o);
                ffma2(hacc[4 + qq * 2], pA, wq);
                ffma2(hacc[5 + qq * 2], pB, wq);
            }
        }
    }

    // epilogue: [row(0=y,1=y+8)][col(0,1)]
    float c0m[2][2], c1m[2][2], rm[4][2][2];
    up2(c0m[0][0], c0m[1][0], hacc[0]); up2(c0m[0][1], c0m[1][1], hacc[1]);
    up2(c1m[0][0], c1m[1][0], hacc[2]); up2(c1m[0][1], c1m[1][1], hacc[3]);
#pragma unroll
    for (int qq = 0; qq < 4; qq++) {
        up2(rm[qq][0][0], rm[qq][1][0], hacc[4 + qq * 2]);
        up2(rm[qq][0][1], rm[qq][1][1], hacc[5 + qq * 2]);
    }

#pragma unroll
    for (int rr = 0; rr < 2; rr++) {
        int yy = oy + rr * 8;
        if (yy >= C3) continue;
#pragma unroll
        for (int cc2 = 0; cc2 < 2; cc2++) {
            int xx = ox + cc2;
            if (xx >= C3) continue;
            float c0 = c0m[rr][cc2], c1 = c1m[rr][cc2];
            float mx = fmaxf(c0, c1);
            float e0 = expf(c0 - mx), e1 = expf(c1 - mx);
            float pr = e1 / (e0 + e1);

            int pix = yy * C3 + xx;
            g_prob[pix] = pr;
            g_reg[pix] = make_float4(rm[0][rr][cc2], rm[1][rr][cc2],
                                     rm[2][rr][cc2], rm[3][rr][cc2]);

            if (pr >= 0.6f) {
                int bin = (int)((pr - 0.6f) * 20480.f);
                if (bin > NBINS - 1) bin = NBINS - 1;
                atomicAdd(&g_hist[bin], 1);
            }
        }
    }
}

// ============ KH: find histogram cutoff bin ============
__global__ void kh() {
    __shared__ int csum[256];
    int t = threadIdx.x;
    int sum = 0;
    for (int b = t * 32; b < t * 32 + 32; b++) sum += g_hist[b];
    csum[t] = sum;
    __syncthreads();
    int chunk = sum;
    for (int off = 1; off < 256; off <<= 1) {
        int v = csum[t] + ((t + off < 256) ? csum[t + off] : 0);
        __syncthreads();
        csum[t] = v;
        __syncthreads();
    }
    int total = csum[0];
    if (t == 0 && total < KTOP) g_cut = 0;
    int suf_excl = (t < 255) ? csum[t + 1] : 0;
    if (suf_excl < KTOP && suf_excl + chunk >= KTOP) {
        int s = suf_excl;
        int B = t * 32;
        for (int b = t * 32 + 31; b >= t * 32; b--) {
            s += g_hist[b];
            if (s >= KTOP) { B = b; break; }
        }
        g_cut = B;
    }
}

// ============ KC: compact candidates >= cutoff bin ============
__global__ void kc() {
    int i = blockIdx.x * 256 + threadIdx.x;
    if (i >= NPIX) return;
    float pr = g_prob[i];
    if (pr < 0.6f) return;
    int bin = (int)((pr - 0.6f) * 20480.f);
    if (bin > NBINS - 1) bin = NBINS - 1;
    if (bin < g_cut) return;
    int pos = atomicAdd(&g_cnt, 1);
    if (pos < CANDMAX) {
        unsigned long long key =
            ((unsigned long long)__float_as_uint(pr) << 32) |
            (unsigned long long)(~(unsigned)i);
        g_cand[pos] = key;
    }
}

// ============ KS: bitonic sort desc + decode boxes ============
__global__ void ks() {
    __shared__ unsigned long long a[CANDMAX];
    int tid = threadIdx.x;
    int cnt = g_cnt;
    if (cnt > CANDMAX) cnt = CANDMAX;
    for (int i = tid; i < CANDMAX; i += 1024) a[i] = (i < cnt) ? g_cand[i] : 0ULL;
    __syncthreads();

    for (int k = 2; k <= CANDMAX; k <<= 1) {
        for (int j = k >> 1; j > 0; j >>= 1) {
            for (int i = tid; i < CANDMAX; i += 1024) {
                int ixj = i ^ j;
                if (ixj > i) {
                    unsigned long long A = a[i], B = a[ixj];
                    bool desc = ((i & k) == 0);
                    if (desc ? (A < B) : (A > B)) { a[i] = B; a[ixj] = A; }
                }
            }
            __syncthreads();
        }
    }

    if (tid < KTOP) {
        unsigned long long key = a[tid];
        unsigned sb = (unsigned)(key >> 32);
        float sc = sb ? __uint_as_float(sb) : -1.0f;
        float x1 = 0.f, y1 = 0.f, x2 = 0.f, y2 = 0.f;
        if (sc >= 0.6f) {
            unsigned idx = ~(unsigned)(key & 0xFFFFFFFFu);
            float4 rg = g_reg[idx];
            float yy = (float)(idx / C3);
            float xx = (float)(idx % C3);
            float cx = (xx * 2.0f + 6.0f) / 0.6f;
            float cy = (yy * 2.0f + 6.0f) / 0.6f;
            const float ww = 12.0f / 0.6f;
            x1 = cx - ww * 0.5f + rg.x * ww;
            y1 = cy - ww * 0.5f + rg.y * ww;
            x2 = cx + ww * 0.5f + rg.z * ww;
            y2 = cy + ww * 0.5f + rg.w * ww;
        }
        g_box5[tid * 5 + 0] = x1;
        g_box5[tid * 5 + 1] = y1;
        g_box5[tid * 5 + 2] = x2;
        g_box5[tid * 5 + 3] = y2;
        g_box5[tid * 5 + 4] = sc;
    }
}

// ============ KM: build suppression bitmasks ============
__global__ void kmask() {
    int i = blockIdx.x;
    int t = threadIdx.x;
    float ax1 = g_box5[i * 5 + 0], ay1 = g_box5[i * 5 + 1];
    float ax2 = g_box5[i * 5 + 2], ay2 = g_box5[i * 5 + 3];
    float bx1 = g_box5[t * 5 + 0], by1 = g_box5[t * 5 + 1];
    float bx2 = g_box5[t * 5 + 2], by2 = g_box5[t * 5 + 3];
    float aar = (ax2 - ax1) * (ay2 - ay1);
    float bar = (bx2 - bx1) * (by2 - by1);
    float xi1 = fmaxf(ax1, bx1), yi1 = fmaxf(ay1, by1);
    float xi2 = fminf(ax2, bx2), yi2 = fminf(ay2, by2);
    float inter = fmaxf(xi2 - xi1, 0.f) * fmaxf(yi2 - yi1, 0.f);
    float iou = inter / (aar + bar - inter + 1e-9f);
    bool gt = (t > i);
    unsigned b0 = __ballot_sync(0xFFFFFFFFu, gt && (iou > 0.5f));
    unsigned b1 = __ballot_sync(0xFFFFFFFFu, gt && (iou > 0.7f));
    if ((t & 31) == 0) {
        g_mask0[i * 16 + (t >> 5)] = b0;
        g_mask1[i * 16 + (t >> 5)] = b1;
    }
}

// ============ KQ: sequential keep-propagation + output ============
__global__ void kseq(float* __restrict__ out) {
    __shared__ unsigned sm[KTOP * 16];
    __shared__ unsigned skw[16];
    int t = threadIdx.x;
    float x1 = g_box5[t * 5 + 0];
    float y1 = g_box5[t * 5 + 1];
    float x2 = g_box5[t * 5 + 2];
    float y2 = g_box5[t * 5 + 3];
    float sc = g_box5[t * 5 + 4];
    unsigned bal = __ballot_sync(0xFFFFFFFFu, sc >= 0.6f);
    if ((t & 31) == 0) skw[t >> 5] = bal;

    for (int pass = 0; pass < 2; pass++) {
        const unsigned* gm = pass ? g_mask1 : g_mask0;
        for (int i = t; i < KTOP * 16; i += 512) sm[i] = gm[i];
        __syncthreads();
        if (t < 32) {
            unsigned k = (t < 16) ? skw[t] : 0u;
            for (int w = 0; w < 16; w++) {
                unsigned done = 0;
                while (true) {
                    unsigned cur = __shfl_sync(0xFFFFFFFFu, k, w) & ~done;
                    if (!cur) break;
                    int b = __ffs(cur) - 1;
                    done |= (1u << b);
                    int i = w * 32 + b;
                    unsigned m = (t < 16) ? sm[i * 16 + t] : 0u;
                    k &= ~m;
                }
            }
            if (t < 16) skw[t] = k;
        }
        __syncthreads();
    }

    float m = ((skw[t >> 5] >> (t & 31)) & 1u) ? 1.f : 0.f;
    out[t * 5 + 0] = x1 * m;
    out[t * 5 + 1] = y1 * m;
    out[t * 5 + 2] = x2 * m;
    out[t * 5 + 3] = y2 * m;
    out[t * 5 + 4] = sc * m;
}

// ---------------- host launcher ----------------
extern "C" void kernel_launch(void* const* d_in, const int* in_sizes, int n_in,
                              void* d_out, int out_size) {
    const float* x = (const float*)d_in[0];

    kpack<<<1, 256>>>((const float*)d_in[1], (const float*)d_in[2], (const float*)d_in[3],
                      (const float*)d_in[4], (const float*)d_in[5], (const float*)d_in[6],
                      (const float*)d_in[7], (const float*)d_in[8], (const float*)d_in[9],
                      (const float*)d_in[10], (const float*)d_in[11],
                      (const float*)d_in[12], (const float*)d_in[13]);

    void* sp = 0; cudaGetSymbolAddress(&sp, g_stage);
    cudaMemcpyToSymbolAsync(cAll, sp, NCONST * sizeof(float), 0, cudaMemcpyDeviceToDevice);
    void* sp2 = 0; cudaGetSymbolAddress(&sp2, g_stage2);
    cudaMemcpyToSymbolAsync(cDup, sp2, 462 * sizeof(ull), 0, cudaMemcpyDeviceToDevice);

    void* hp = 0; cudaGetSymbolAddress(&hp, g_hist);
    cudaMemsetAsync(hp, 0, NBINS * sizeof(int));
    void* cp = 0; cudaGetSymbolAddress(&cp, g_cnt);
    cudaMemsetAsync(cp, 0, sizeof(int));

    cudaFuncSetAttribute(k2, cudaFuncAttributeMaxDynamicSharedMemorySize, K2_SMEM_BYTES);
    cudaFuncSetAttribute(k3, cudaFuncAttributeMaxDynamicSharedMemorySize, K3_SMEM_BYTES);

    k1<<<dim3(64, 64), dim3(16, 16)>>>(x);
    k2<<<dim3(32, 64), dim3(16, 8), K2_SMEM_BYTES>>>();
    k3<<<dim3(32, 64), dim3(16, 8), K3_SMEM_BYTES>>>();
    kh<<<1, 256>>>();
    kc<<<(NPIX + 255) / 256, 256>>>();
    ks<<<1, 1024>>>();
    kmask<<<KTOP, KTOP>>>();
    kseq<<<1, 512>>>((float*)d_out);
}

// round 13
// speedup vs baseline: 1.4937x; 1.0305x over previous
#include <cuda_runtime.h>
#include <math.h>
#include <stdint.h>

// ---------------- problem constants ----------------
#define H_IN 2048
#define W_IN 2048
#define P1   1023            // after conv1(2046) + maxpool2
#define C2   1021            // after conv2
#define H2S  1024            // padded row stride for h2
#define C3   1019            // after conv3
#define NPIX (C3*C3)         // 1038361
#define NBINS 8192
#define CANDMAX 4096
#define KTOP 512

typedef unsigned long long ull;

// ---------------- scratch (device globals) ----------
__device__ float g_pool1[10 * P1 * P1];
__device__ float g_h2p[16 * C2 * H2S];      // padded stride 1024
__device__ float g_prob[NPIX];
__device__ float4 g_reg[NPIX];
__device__ int   g_hist[NBINS];
__device__ int   g_cut;
__device__ int   g_cnt;
__device__ unsigned long long g_cand[CANDMAX];
__device__ float g_box5[KTOP * 5];
__device__ unsigned g_mask0[KTOP * 16];
__device__ unsigned g_mask1[KTOP * 16];
__device__ float g_stage[6632];
__device__ ull   g_stage2[462];
// oo-pair-interleaved duplicated weights:
//   g_wq2[(c*8+op)*9+k] = { {w2(2op,c,k)}dup, {w2(2op+1,c,k)}dup }
//   g_wq3[((og*16+c)*4+op)*9+k] = { {w3(og*8+2op,c,k)}dup, {w3(og*8+2op+1,c,k)}dup }
__device__ ulonglong2 g_wq2[10 * 8 * 9];     // 720
__device__ ulonglong2 g_wq3[4 * 16 * 4 * 9]; // 2304

// ---------------- packed constant scalars -------
#define OW1 0
#define OB1 270
#define OP1 280
#define OW2 290
#define OB2 1730
#define OP2 1746
#define OW3 1762
#define OB3 6370
#define OP3 6402
#define OWA 6434
#define OBA 6498
#define OWB 6500
#define OBB 6628
#define NCONST 6632
__constant__ float cAll[NCONST];
__constant__ ull cDup[462];   // k1 weights (270), head wa (64), head wb (128)

#define CB1(i) cAll[OB1 + (i)]
#define CP1(i) cAll[OP1 + (i)]
#define CB2(i) cAll[OB2 + (i)]
#define CP2(i) cAll[OP2 + (i)]
#define CB3(i) cAll[OB3 + (i)]
#define CP3(i) cAll[OP3 + (i)]
#define CBA(i) cAll[OBA + (i)]
#define CBB(i) cAll[OBB + (i)]
#define D1(i)  cDup[(i)]
#define DWA(i) cDup[270 + (i)]
#define DWB(i) cDup[334 + (i)]

// ---------------- f32x2 helpers ----------------
__device__ __forceinline__ ull pk2(float lo, float hi) {
    ull r; asm("mov.b64 %0, {%1, %2};" : "=l"(r) : "f"(lo), "f"(hi)); return r;
}
__device__ __forceinline__ void up2(float& lo, float& hi, ull v) {
    asm("mov.b64 {%0, %1}, %2;" : "=f"(lo), "=f"(hi) : "l"(v));
}
__device__ __forceinline__ void ffma2(ull& d, ull a, ull b) {
    asm("fma.rn.f32x2 %0, %1, %2, %0;" : "+l"(d) : "l"(a), "l"(b));
}

// ============ KP: pack weights ============
__global__ void kpack(const float* w1, const float* b1, const float* p1,
                      const float* w2, const float* b2, const float* p2,
                      const float* w3, const float* b3, const float* p3,
                      const float* wa, const float* ba,
                      const float* wb, const float* bb) {
    int t = threadIdx.x;
    for (int i = t; i < 270; i += 256) g_stage[OW1 + i] = w1[i];
    if (t < 10) g_stage[OB1 + t] = b1[t];
    if (t < 10) g_stage[OP1 + t] = p1[t];
    for (int i = t; i < 1440; i += 256) g_stage[OW2 + i] = w2[i];
    if (t < 16) g_stage[OB2 + t] = b2[t];
    if (t < 16) g_stage[OP2 + t] = p2[t];
    for (int i = t; i < 4608; i += 256) g_stage[OW3 + i] = w3[i];
    if (t < 32) g_stage[OB3 + t] = b3[t];
    if (t < 32) g_stage[OP3 + t] = p3[t];
    if (t < 64) g_stage[OWA + t] = wa[t];
    if (t < 2)  g_stage[OBA + t] = ba[t];
    for (int i = t; i < 128; i += 256) g_stage[OWB + i] = wb[i];
    if (t < 4)  g_stage[OBB + t] = bb[t];

    for (int i = t; i < 270; i += 256) {
        unsigned u = __float_as_uint(w1[i]);
        g_stage2[i] = ((ull)u << 32) | u;
    }
    if (t < 64) {
        unsigned u = __float_as_uint(wa[t]);
        g_stage2[270 + t] = ((ull)u << 32) | u;
    }
    for (int i = t; i < 128; i += 256) {
        unsigned u = __float_as_uint(wb[i]);
        g_stage2[334 + i] = ((ull)u << 32) | u;
    }

    // k2: oo-pair interleave
    ull* q2 = (ull*)g_wq2;
    for (int idx = t; idx < 1440; idx += 256) {
        int k = idx % 9, rest = idx / 9;
        int o = rest % 16, c = rest / 16;
        unsigned u = __float_as_uint(w2[o * 90 + c * 9 + k]);
        ull d = ((ull)u << 32) | u;
        q2[((c * 8 + (o >> 1)) * 9 + k) * 2 + (o & 1)] = d;
    }
    // k3: oo-pair interleave, grouped by output-quarter og
    ull* q3 = (ull*)g_wq3;
    for (int idx = t; idx < 4608; idx += 256) {
        int k = idx % 9, rest = idx / 9;
        int o = rest % 32, c = rest / 32;
        int og = o >> 3, oo = o & 7, op = oo >> 1;
        unsigned u = __float_as_uint(w3[o * 144 + c * 9 + k]);
        ull d = ((ull)u << 32) | u;
        q3[(((og * 16 + c) * 4 + op) * 9 + k) * 2 + (oo & 1)] = d;
    }
}

// ============ K1: conv1(3->10,3x3) + PReLU + maxpool2, f32x2 ============
__global__ __launch_bounds__(256) void k1(const float* __restrict__ x) {
    int j = blockIdx.x * 16 + threadIdx.x;
    int i = blockIdx.y * 16 + threadIdx.y;
    if (i >= P1 || j >= P1) return;

    ull a01[10], a23[10];
#pragma unroll
    for (int co = 0; co < 10; co++) {
        float b = CB1(co);
        a01[co] = pk2(b, b);
        a23[co] = pk2(b, b);
    }

#pragma unroll
    for (int c = 0; c < 3; c++) {
        const float* xp = x + c * H_IN * W_IN + (2 * i) * W_IN + 2 * j;
        ull t2[4][3];
#pragma unroll
        for (int a = 0; a < 4; a++) {
            const float2* rp = reinterpret_cast<const float2*>(xp + a * W_IN);
            float2 u = rp[0], v = rp[1];
            t2[a][0] = pk2(u.x, u.y);
            t2[a][1] = pk2(u.y, v.x);
            t2[a][2] = pk2(v.x, v.y);
        }
#pragma unroll
        for (int co = 0; co < 10; co++)
#pragma unroll
            for (int dy = 0; dy < 3; dy++)
#pragma unroll
                for (int dx = 0; dx < 3; dx++) {
                    ull w = D1(((co * 3 + c) * 3 + dy) * 3 + dx);
                    ffma2(a01[co], t2[dy][dx], w);
                    ffma2(a23[co], t2[dy + 1][dx], w);
                }
    }

#pragma unroll
    for (int co = 0; co < 10; co++) {
        float a00, a01v, a10, a11;
        up2(a00, a01v, a01[co]);
        up2(a10, a11, a23[co]);
        float al = CP1(co);
        a00  = (a00  >= 0.f) ? a00  : al * a00;
        a01v = (a01v >= 0.f) ? a01v : al * a01v;
        a10  = (a10  >= 0.f) ? a10  : al * a10;
        a11  = (a11  >= 0.f) ? a11  : al * a11;
        g_pool1[co * P1 * P1 + i * P1 + j] = fmaxf(fmaxf(a00, a01v), fmaxf(a10, a11));
    }
}

// ============ K2: conv2(10->16) + PReLU, row-pair f32x2, 2 cols/thread ====
#define K2_DATA2 (10 * 10 * 34)                    // float2 count = 3400
#define K2_SMEM_BYTES (K2_DATA2 * 8 + 720 * 16)    // 27200 + 11520 = 38720

__global__ __launch_bounds__(128, 4) void k2() {
    extern __shared__ float dy2[];
    float2* S = (float2*)dy2;
    ulonglong2* wsm = (ulonglong2*)(dy2 + K2_DATA2 * 2);

    int tx = threadIdx.x, ty = threadIdx.y;       // (16, 8)
    int tid = ty * 16 + tx;
    int ox0 = blockIdx.x * 32, oy0 = blockIdx.y * 16;
    int ox = ox0 + 2 * tx, oy = oy0 + ty;

    {
        float4* wv = (float4*)wsm;
        const float4* wg = (const float4*)g_wq2;
        for (int i = tid; i < 720; i += 128) wv[i] = wg[i];
    }
    // stage tile: S[(c*10+r)*34 + x] = {in[oy0+r][x], in[oy0+r+8][x]}
    for (int i = tid; i < 10 * 10 * 34; i += 128) {
        int c = i / 340; int rem = i - c * 340;
        int r = rem / 34; int xx = rem - r * 34;
        int gx = ox0 + xx;
        int gyl = oy0 + r, gyh = gyl + 8;
        const float* pl = g_pool1 + c * P1 * P1;
        float lo = (gyl < P1 && gx < P1) ? pl[gyl * P1 + gx] : 0.f;
        float hi = (gyh < P1 && gx < P1) ? pl[gyh * P1 + gx] : 0.f;
        S[(c * 10 + r) * 34 + xx] = make_float2(lo, hi);
    }
    __syncthreads();

    ull accA[16], accB[16];   // accA = col ox (rows y,y+8), accB = col ox+1
#pragma unroll
    for (int o = 0; o < 16; o++) {
        float b = CB2(o);
        accA[o] = pk2(b, b);
        accB[o] = pk2(b, b);
    }

#pragma unroll 2
    for (int c = 0; c < 10; c++) {
        ull t[3][4];
#pragma unroll
        for (int dy = 0; dy < 3; dy++) {
            const ull* rp = (const ull*)&S[(c * 10 + ty + dy) * 34 + 2 * tx];
            ulonglong2 u0 = *(const ulonglong2*)rp;
            ulonglong2 u1 = *(const ulonglong2*)(rp + 2);
            t[dy][0] = u0.x; t[dy][1] = u0.y; t[dy][2] = u1.x; t[dy][3] = u1.y;
        }
        const ulonglong2* wc = wsm + c * 72;
#pragma unroll
        for (int op = 0; op < 8; op++) {
            const ulonglong2* w = wc + op * 9;
#pragma unroll
            for (int k = 0; k < 9; k++) {
                ulonglong2 W = w[k];
                int dyk = k / 3, dxk = k % 3;
                ffma2(accA[2 * op],     t[dyk][dxk],     W.x);
                ffma2(accB[2 * op],     t[dyk][dxk + 1], W.x);
                ffma2(accA[2 * op + 1], t[dyk][dxk],     W.y);
                ffma2(accB[2 * op + 1], t[dyk][dxk + 1], W.y);
            }
        }
    }

#pragma unroll
    for (int o = 0; o < 16; o++) {
        float al = CP2(o);
        float aL, aH, bL, bH;
        up2(aL, aH, accA[o]);
        up2(bL, bH, accB[o]);
        aL = (aL >= 0.f) ? aL : al * aL;
        aH = (aH >= 0.f) ? aH : al * aH;
        bL = (bL >= 0.f) ? bL : al * bL;
        bH = (bH >= 0.f) ? bH : al * bH;
        float* pl = g_h2p + o * (C2 * H2S);
        if (oy < C2) {
            if (ox + 1 < C2) *reinterpret_cast<float2*>(pl + oy * H2S + ox) = make_float2(aL, bL);
            else if (ox < C2) pl[oy * H2S + ox] = aL;
        }
        int oy2 = oy + 8;
        if (oy2 < C2) {
            if (ox + 1 < C2) *reinterpret_cast<float2*>(pl + oy2 * H2S + ox) = make_float2(aH, bH);
            else if (ox < C2) pl[oy2 * H2S + ox] = aH;
        }
    }
}

// ============ K3: conv3(16->32) + PReLU + heads + softmax + hist ==========
#define K3_DATA2 (16 * 10 * 34)                    // float2 count = 5440
#define K3_SMEM_BYTES (K3_DATA2 * 8 + 576 * 16)    // 43520 + 9216 = 52736

__global__ __launch_bounds__(128, 4) void k3() {
    extern __shared__ float dy3[];
    float2* S = (float2*)dy3;
    ulonglong2* wsm = (ulonglong2*)(dy3 + K3_DATA2 * 2);

    int tx = threadIdx.x, ty = threadIdx.y;       // (16, 8)
    int tid = ty * 16 + tx;
    int ox0 = blockIdx.x * 32, oy0 = blockIdx.y * 16;
    int ox = ox0 + 2 * tx, oy = oy0 + ty;

    // stage tile once: S[(c*10+r)*34 + x] = {h2[oy0+r][x], h2[oy0+r+8][x]}
    for (int i = tid; i < 16 * 10 * 17; i += 128) {
        int c = i / 170; int rem = i - c * 170;
        int r = rem / 17; int j = rem - r * 17;
        int gx = ox0 + 2 * j;
        int gyl = oy0 + r, gyh = gyl + 8;
        const float* pl = g_h2p + c * (C2 * H2S);
        float2 a = make_float2(0.f, 0.f), b = make_float2(0.f, 0.f);
        if (gyl < C2) {
            if (gx + 1 < C2) a = *reinterpret_cast<const float2*>(pl + gyl * H2S + gx);
            else if (gx < C2) a.x = pl[gyl * H2S + gx];
        }
        if (gyh < C2) {
            if (gx + 1 < C2) b = *reinterpret_cast<const float2*>(pl + gyh * H2S + gx);
            else if (gx < C2) b.x = pl[gyh * H2S + gx];
        }
        float2* dst = S + (c * 10 + r) * 34 + 2 * j;
        dst[0] = make_float2(a.x, b.x);
        dst[1] = make_float2(a.y, b.y);
    }

    // head accumulators: c0,c1,r0..r3 x {colA, colB}; lanes = rows (y, y+8)
    ull hacc[12];
    {
        float b0 = CBA(0), b1 = CBA(1);
        hacc[0] = pk2(b0, b0); hacc[1] = pk2(b0, b0);
        hacc[2] = pk2(b1, b1); hacc[3] = pk2(b1, b1);
#pragma unroll
        for (int qq = 0; qq < 4; qq++) {
            float b = CBB(qq);
            hacc[4 + qq * 2] = pk2(b, b);
            hacc[5 + qq * 2] = pk2(b, b);
        }
    }

#pragma unroll 1
    for (int og = 0; og < 4; og++) {
        __syncthreads();   // og=0: also covers tile staging
        {
            float4* wv = (float4*)wsm;
            const float4* wg = (const float4*)g_wq3 + og * 576;
            for (int i = tid; i < 576; i += 128) wv[i] = wg[i];
        }
        __syncthreads();

        ull accA[8], accB[8];
#pragma unroll
        for (int oo = 0; oo < 8; oo++) {
            float b = CB3(og * 8 + oo);
            ull bb = pk2(b, b);
            accA[oo] = bb; accB[oo] = bb;
        }

#pragma unroll 2
        for (int c = 0; c < 16; c++) {
            ull t[3][4];
#pragma unroll
            for (int dy = 0; dy < 3; dy++) {
                const ull* rp = (const ull*)&S[(c * 10 + ty + dy) * 34 + 2 * tx];
                ulonglong2 u0 = *(const ulonglong2*)rp;
                ulonglong2 u1 = *(const ulonglong2*)(rp + 2);
                t[dy][0] = u0.x; t[dy][1] = u0.y; t[dy][2] = u1.x; t[dy][3] = u1.y;
            }
            const ulonglong2* wc = wsm + c * 36;
#pragma unroll
            for (int op = 0; op < 4; op++) {
                const ulonglong2* w = wc + op * 9;
#pragma unroll
                for (int k = 0; k < 9; k++) {
                    ulonglong2 W = w[k];
                    int dyk = k / 3, dxk = k % 3;
                    ffma2(accA[2 * op],     t[dyk][dxk],     W.x);
                    ffma2(accB[2 * op],     t[dyk][dxk + 1], W.x);
                    ffma2(accA[2 * op + 1], t[dyk][dxk],     W.y);
                    ffma2(accB[2 * op + 1], t[dyk][dxk + 1], W.y);
                }
            }
        }

        // PReLU + incremental head accumulation for this quarter
#pragma unroll
        for (int oo = 0; oo < 8; oo++) {
            int o = og * 8 + oo;
            float al = CP3(o);
            float aL, aH, bL, bH;
            up2(aL, aH, accA[oo]);
            up2(bL, bH, accB[oo]);
            aL = (aL >= 0.f) ? aL : al * aL;
            aH = (aH >= 0.f) ? aH : al * aH;
            bL = (bL >= 0.f) ? bL : al * bL;
            bH = (bH >= 0.f) ? bH : al * bH;
            ull pA = pk2(aL, aH), pB = pk2(bL, bH);
            ull wa0 = DWA(o), wa1 = DWA(32 + o);
            ffma2(hacc[0], pA, wa0); ffma2(hacc[1], pB, wa0);
            ffma2(hacc[2], pA, wa1); ffma2(hacc[3], pB, wa1);
#pragma unroll
            for (int qq = 0; qq < 4; qq++) {
                ull wq = DWB(qq * 32 + o);
                ffma2(hacc[4 + qq * 2], pA, wq);
                ffma2(hacc[5 + qq * 2], pB, wq);
            }
        }
    }

    // epilogue: [row(0=y,1=y+8)][col(0,1)]
    float c0m[2][2], c1m[2][2], rm[4][2][2];
    up2(c0m[0][0], c0m[1][0], hacc[0]); up2(c0m[0][1], c0m[1][1], hacc[1]);
    up2(c1m[0][0], c1m[1][0], hacc[2]); up2(c1m[0][1], c1m[1][1], hacc[3]);
#pragma unroll
    for (int qq = 0; qq < 4; qq++) {
        up2(rm[qq][0][0], rm[qq][1][0], hacc[4 + qq * 2]);
        up2(rm[qq][0][1], rm[qq][1][1], hacc[5 + qq * 2]);
    }

#pragma unroll
    for (int rr = 0; rr < 2; rr++) {
        int yy = oy + rr * 8;
        if (yy >= C3) continue;
#pragma unroll
        for (int cc2 = 0; cc2 < 2; cc2++) {
            int xx = ox + cc2;
            if (xx >= C3) continue;
            float c0 = c0m[rr][cc2], c1 = c1m[rr][cc2];
            float mx = fmaxf(c0, c1);
            float e0 = expf(c0 - mx), e1 = expf(c1 - mx);
            float pr = e1 / (e0 + e1);

            int pix = yy * C3 + xx;
            g_prob[pix] = pr;
            g_reg[pix] = make_float4(rm[0][rr][cc2], rm[1][rr][cc2],
                                     rm[2][rr][cc2], rm[3][rr][cc2]);

            if (pr >= 0.6f) {
                int bin = (int)((pr - 0.6f) * 20480.f);
                if (bin > NBINS - 1) bin = NBINS - 1;
                atomicAdd(&g_hist[bin], 1);
            }
        }
    }
}

// ============ KH: find histogram cutoff bin ============
__global__ void kh() {
    __shared__ int csum[256];
    int t = threadIdx.x;
    int sum = 0;
    for (int b = t * 32; b < t * 32 + 32; b++) sum += g_hist[b];
    csum[t] = sum;
    __syncthreads();
    int chunk = sum;
    for (int off = 1; off < 256; off <<= 1) {
        int v = csum[t] + ((t + off < 256) ? csum[t + off] : 0);
        __syncthreads();
        csum[t] = v;
        __syncthreads();
    }
    int total = csum[0];
    if (t == 0 && total < KTOP) g_cut = 0;
    int suf_excl = (t < 255) ? csum[t + 1] : 0;
    if (suf_excl < KTOP && suf_excl + chunk >= KTOP) {
        int s = suf_excl;
        int B = t * 32;
        for (int b = t * 32 + 31; b >= t * 32; b--) {
            s += g_hist[b];
            if (s >= KTOP) { B = b; break; }
        }
        g_cut = B;
    }
}

// ============ KC: compact candidates >= cutoff bin ============
__global__ void kc() {
    int i = blockIdx.x * 256 + threadIdx.x;
    if (i >= NPIX) return;
    float pr = g_prob[i];
    if (pr < 0.6f) return;
    int bin = (int)((pr - 0.6f) * 20480.f);
    if (bin > NBINS - 1) bin = NBINS - 1;
    if (bin < g_cut) return;
    int pos = atomicAdd(&g_cnt, 1);
    if (pos < CANDMAX) {
        unsigned long long key =
            ((unsigned long long)__float_as_uint(pr) << 32) |
            (unsigned long long)(~(unsigned)i);
        g_cand[pos] = key;
    }
}

// ============ KS: bitonic sort desc + decode boxes ============
__global__ void ks() {
    __shared__ unsigned long long a[CANDMAX];
    int tid = threadIdx.x;
    int cnt = g_cnt;
    if (cnt > CANDMAX) cnt = CANDMAX;
    for (int i = tid; i < CANDMAX; i += 1024) a[i] = (i < cnt) ? g_cand[i] : 0ULL;
    __syncthreads();

    for (int k = 2; k <= CANDMAX; k <<= 1) {
        for (int j = k >> 1; j > 0; j >>= 1) {
            for (int i = tid; i < CANDMAX; i += 1024) {
                int ixj = i ^ j;
                if (ixj > i) {
                    unsigned long long A = a[i], B = a[ixj];
                    bool desc = ((i & k) == 0);
                    if (desc ? (A < B) : (A > B)) { a[i] = B; a[ixj] = A; }
                }
            }
            __syncthreads();
        }
    }

    if (tid < KTOP) {
        unsigned long long key = a[tid];
        unsigned sb = (unsigned)(key >> 32);
        float sc = sb ? __uint_as_float(sb) : -1.0f;
        float x1 = 0.f, y1 = 0.f, x2 = 0.f, y2 = 0.f;
        if (sc >= 0.6f) {
            unsigned idx = ~(unsigned)(key & 0xFFFFFFFFu);
            float4 rg = g_reg[idx];
            float yy = (float)(idx / C3);
            float xx = (float)(idx % C3);
            float cx = (xx * 2.0f + 6.0f) / 0.6f;
            float cy = (yy * 2.0f + 6.0f) / 0.6f;
            const float ww = 12.0f / 0.6f;
            x1 = cx - ww * 0.5f + rg.x * ww;
            y1 = cy - ww * 0.5f + rg.y * ww;
            x2 = cx + ww * 0.5f + rg.z * ww;
            y2 = cy + ww * 0.5f + rg.w * ww;
        }
        g_box5[tid * 5 + 0] = x1;
        g_box5[tid * 5 + 1] = y1;
        g_box5[tid * 5 + 2] = x2;
        g_box5[tid * 5 + 3] = y2;
        g_box5[tid * 5 + 4] = sc;
    }
}

// ============ KM: build suppression bitmasks ============
__global__ void kmask() {
    int i = blockIdx.x;
    int t = threadIdx.x;
    float ax1 = g_box5[i * 5 + 0], ay1 = g_box5[i * 5 + 1];
    float ax2 = g_box5[i * 5 + 2], ay2 = g_box5[i * 5 + 3];
    float bx1 = g_box5[t * 5 + 0], by1 = g_box5[t * 5 + 1];
    float bx2 = g_box5[t * 5 + 2], by2 = g_box5[t * 5 + 3];
    float aar = (ax2 - ax1) * (ay2 - ay1);
    float bar = (bx2 - bx1) * (by2 - by1);
    float xi1 = fmaxf(ax1, bx1), yi1 = fmaxf(ay1, by1);
    float xi2 = fminf(ax2, bx2), yi2 = fminf(ay2, by2);
    float inter = fmaxf(xi2 - xi1, 0.f) * fmaxf(yi2 - yi1, 0.f);
    float iou = inter / (aar + bar - inter + 1e-9f);
    bool gt = (t > i);
    unsigned b0 = __ballot_sync(0xFFFFFFFFu, gt && (iou > 0.5f));
    unsigned b1 = __ballot_sync(0xFFFFFFFFu, gt && (iou > 0.7f));
    if ((t & 31) == 0) {
        g_mask0[i * 16 + (t >> 5)] = b0;
        g_mask1[i * 16 + (t >> 5)] = b1;
    }
}

// ============ KQ: sequential keep-propagation + output ============
__global__ void kseq(float* __restrict__ out) {
    __shared__ unsigned sm[KTOP * 16];
    __shared__ unsigned skw[16];
    int t = threadIdx.x;
    float x1 = g_box5[t * 5 + 0];
    float y1 = g_box5[t * 5 + 1];
    float x2 = g_box5[t * 5 + 2];
    float y2 = g_box5[t * 5 + 3];
    float sc = g_box5[t * 5 + 4];
    unsigned bal = __ballot_sync(0xFFFFFFFFu, sc >= 0.6f);
    if ((t & 31) == 0) skw[t >> 5] = bal;

    for (int pass = 0; pass < 2; pass++) {
        const unsigned* gm = pass ? g_mask1 : g_mask0;
        for (int i = t; i < KTOP * 16; i += 512) sm[i] = gm[i];
        __syncthreads();
        if (t < 32) {
            unsigned k = (t < 16) ? skw[t] : 0u;
            for (int w = 0; w < 16; w++) {
                unsigned done = 0;
                while (true) {
                    unsigned cur = __shfl_sync(0xFFFFFFFFu, k, w) & ~done;
                    if (!cur) break;
                    int b = __ffs(cur) - 1;
                    done |= (1u << b);
                    int i = w * 32 + b;
                    unsigned m = (t < 16) ? sm[i * 16 + t] : 0u;
                    k &= ~m;
                }
            }
            if (t < 16) skw[t] = k;
        }
        __syncthreads();
    }

    float m = ((skw[t >> 5] >> (t & 31)) & 1u) ? 1.f : 0.f;
    out[t * 5 + 0] = x1 * m;
    out[t * 5 + 1] = y1 * m;
    out[t * 5 + 2] = x2 * m;
    out[t * 5 + 3] = y2 * m;
    out[t * 5 + 4] = sc * m;
}

// ---------------- host launcher ----------------
extern "C" void kernel_launch(void* const* d_in, const int* in_sizes, int n_in,
                              void* d_out, int out_size) {
    const float* x = (const float*)d_in[0];

    kpack<<<1, 256>>>((const float*)d_in[1], (const float*)d_in[2], (const float*)d_in[3],
                      (const float*)d_in[4], (const float*)d_in[5], (const float*)d_in[6],
                      (const float*)d_in[7], (const float*)d_in[8], (const float*)d_in[9],
                      (const float*)d_in[10], (const float*)d_in[11],
                      (const float*)d_in[12], (const float*)d_in[13]);

    void* sp = 0; cudaGetSymbolAddress(&sp, g_stage);
    cudaMemcpyToSymbolAsync(cAll, sp, NCONST * sizeof(float), 0, cudaMemcpyDeviceToDevice);
    void* sp2 = 0; cudaGetSymbolAddress(&sp2, g_stage2);
    cudaMemcpyToSymbolAsync(cDup, sp2, 462 * sizeof(ull), 0, cudaMemcpyDeviceToDevice);

    void* hp = 0; cudaGetSymbolAddress(&hp, g_hist);
    cudaMemsetAsync(hp, 0, NBINS * sizeof(int));
    void* cp = 0; cudaGetSymbolAddress(&cp, g_cnt);
    cudaMemsetAsync(cp, 0, sizeof(int));

    cudaFuncSetAttribute(k2, cudaFuncAttributeMaxDynamicSharedMemorySize, K2_SMEM_BYTES);
    cudaFuncSetAttribute(k3, cudaFuncAttributeMaxDynamicSharedMemorySize, K3_SMEM_BYTES);

    k1<<<dim3(64, 64), dim3(16, 16)>>>(x);
    k2<<<dim3(32, 64), dim3(16, 8), K2_SMEM_BYTES>>>();
    k3<<<dim3(32, 64), dim3(16, 8), K3_SMEM_BYTES>>>();
    kh<<<1, 256>>>();
    kc<<<(NPIX + 255) / 256, 256>>>();
    ks<<<1, 1024>>>();
    kmask<<<KTOP, KTOP>>>();
    kseq<<<1, 512>>>((float*)d_out);
}